// round 11
// baseline (speedup 1.0000x reference)
#include <cuda_runtime.h>
#include <cuda_bf16.h>
#include <cuda_fp16.h>
#include <math.h>
#include <stdint.h>

// Problem dims
#define BB 64
#define SS 50
#define EE 512
#define HH 1024
#define VTS 32000
#define NSTEP 49
#define MPROJ (NSTEP*BB)   /* 3136 */
#define MPAD  3200
#define G4H 4096
#define KSPLIT 8
#define KCHUNK 128         /* 1024/8 */
#define KA 1024            /* projection K */
#define DCTA 256           /* decoder grid */

typedef unsigned long long ull;

// ---------- packed f32x2 helpers ----------
__device__ __forceinline__ ull dup2(float x){
    ull r; asm("mov.b64 %0, {%1, %1};" : "=l"(r) : "f"(x)); return r;
}
__device__ __forceinline__ void ffma2(ull &d, ull a, ull b){
    asm("fma.rn.f32x2 %0, %1, %2, %0;" : "+l"(d) : "l"(a), "l"(b));
}
__device__ __forceinline__ float2 unpk(ull v){
    float2 f; asm("mov.b64 {%0, %1}, %2;" : "=f"(f.x), "=f"(f.y) : "l"(v)); return f;
}

// ---------- baseline-PTX tensor helpers ----------
__device__ __forceinline__ uint32_t smem_u32(const void* p){
    uint32_t a;
    asm("{ .reg .u64 t; cvta.to.shared.u64 t, %1; cvt.u32.u64 %0, t; }" : "=r"(a) : "l"(p));
    return a;
}
__device__ __forceinline__ void cpasync16(uint32_t dst, const void* src){
    asm volatile("cp.async.cg.shared.global [%0], [%1], 16;" :: "r"(dst), "l"(src));
}
__device__ __forceinline__ void cp_commit(){
    asm volatile("cp.async.commit_group;");
}
__device__ __forceinline__ void ldm4(uint32_t* r, uint32_t a){
    asm volatile("ldmatrix.sync.aligned.m8n8.x4.shared.b16 {%0,%1,%2,%3}, [%4];"
        : "=r"(r[0]), "=r"(r[1]), "=r"(r[2]), "=r"(r[3]) : "r"(a));
}
__device__ __forceinline__ void mma16816h(float* c, const uint32_t* a, uint32_t b0, uint32_t b1){
    asm volatile("mma.sync.aligned.m16n8k16.row.col.f32.f16.f16.f32 "
        "{%0,%1,%2,%3}, {%4,%5,%6,%7}, {%8,%9}, {%0,%1,%2,%3};"
        : "+f"(c[0]), "+f"(c[1]), "+f"(c[2]), "+f"(c[3])
        : "r"(a[0]), "r"(a[1]), "r"(a[2]), "r"(a[3]), "r"(b0), "r"(b1));
}

// ---------- scratch ----------
__device__ float g_enc_out[BB*SS*EE];
__device__ float g_avg[BB*EE];
__device__ float g_ctx[BB*EE];
__device__ float g_h[BB*HH];
__device__ float g_c[BB*HH];
__device__ float g_gconst[BB*G4H];
__device__ float g_part[KSPLIT*BB*G4H];
__device__ float g_pre[MPAD*G4H];
__device__ __half g_Ah[(size_t)MPAD*KA];   // rows >= 3136 stay zero (.bss)
__device__ __half g_Bh[(size_t)VTS*KA];

// ---------- dataflow decoder sync state ----------
__device__ int g_gcnt[NSTEP][8];   // gates-GEMM arrivals per h-tile (full = 32)
__device__ int g_hcnt[NSTEP][8];   // lstm arrivals per h-tile (full = 32)

__global__ void reset_flags()
{
    int i = blockIdx.x*blockDim.x + threadIdx.x;
    if (i < NSTEP*8){ ((int*)g_gcnt)[i] = 0; ((int*)g_hcnt)[i] = 0; }
}

__device__ __forceinline__ int ldcg_i(const int* p){
    int v; asm volatile("ld.global.cg.b32 %0, [%1];" : "=r"(v) : "l"(p)); return v;
}

// ============================================================
// Encoder GEMM (fp32 FFMA2)
// ============================================================
__global__ __launch_bounds__(256)
void enc_gemm(const int* __restrict__ src, const int* __restrict__ pos,
              const float* __restrict__ enc_emb, const float* __restrict__ pos_emb,
              const float* __restrict__ cat_W, const float* __restrict__ cat_b)
{
    __shared__ __align__(16) float As[128*20];
    __shared__ __align__(16) float Bs[16*132];
    const int m0 = blockIdx.x * 128;
    const int n0 = blockIdx.y * 128;
    const int tid = threadIdx.x;
    const int tx = tid & 15, ty = tid >> 4;

    ull acc[8][2][2];
    #pragma unroll
    for (int i=0;i<8;i++)
        #pragma unroll
        for (int q=0;q<2;q++){ acc[i][q][0]=0ull; acc[i][q][1]=0ull; }

    for (int kt = 0; kt < 1024; kt += 16){
        #pragma unroll
        for (int l=0;l<2;l++){
            int f4 = tid + 256*l;
            int row = f4 >> 2, k4 = (f4 & 3) << 2;
            int kg = kt + k4;
            int r = m0 + row;
            float4 v;
            if (kg < 512) v = *(const float4*)(enc_emb + (size_t)src[r]*512 + kg);
            else          v = *(const float4*)(pos_emb + (size_t)pos[r]*512 + (kg - 512));
            *(float4*)(As + row*20 + k4) = v;
        }
        #pragma unroll
        for (int l=0;l<2;l++){
            int f4 = tid + 256*l;
            int row = f4 >> 2, k4 = (f4 & 3) << 2;
            float4 v = *(const float4*)(cat_W + (size_t)(n0+row)*1024 + kt + k4);
            Bs[(k4+0)*132 + row] = v.x;
            Bs[(k4+1)*132 + row] = v.y;
            Bs[(k4+2)*132 + row] = v.z;
            Bs[(k4+3)*132 + row] = v.w;
        }
        __syncthreads();
        #pragma unroll
        for (int kq=0;kq<4;kq++){
            float4 av[8];
            #pragma unroll
            for (int i=0;i<8;i++) av[i] = *(const float4*)(As + (ty*8+i)*20 + kq*4);
            #pragma unroll
            for (int kk=0;kk<4;kk++){
                ull a2[8];
                #pragma unroll
                for (int i=0;i<8;i++){
                    float a = (kk==0)?av[i].x:(kk==1)?av[i].y:(kk==2)?av[i].z:av[i].w;
                    a2[i] = dup2(a);
                }
                const int k = kq*4+kk;
                #pragma unroll
                for (int q=0;q<2;q++){
                    ulonglong2 bv = *(const ulonglong2*)(Bs + k*132 + tx*4 + q*64);
                    #pragma unroll
                    for (int i=0;i<8;i++){ ffma2(acc[i][q][0], a2[i], bv.x);
                                           ffma2(acc[i][q][1], a2[i], bv.y); }
                }
            }
        }
        __syncthreads();
    }
    #pragma unroll
    for (int i=0;i<8;i++){
        int gm = m0 + ty*8 + i;
        #pragma unroll
        for (int q=0;q<2;q++){
            int gn = n0 + tx*4 + q*64;
            float2 p0 = unpk(acc[i][q][0]);
            float2 p1 = unpk(acc[i][q][1]);
            float4 bb = *(const float4*)(cat_b + gn);
            *(float4*)(g_enc_out + (size_t)gm*512 + gn) =
                make_float4(p0.x+bb.x, p0.y+bb.y, p1.x+bb.z, p1.y+bb.w);
        }
    }
}

__global__ void avg_kernel()
{
    int b = blockIdx.x, e = threadIdx.x;
    float s = 0.f;
    #pragma unroll 5
    for (int si=0; si<SS; si++) s += g_enc_out[(b*SS+si)*EE + e];
    g_avg[b*EE + e] = s * (1.0f/50.0f);
}

__global__ void h0_kernel(const float* __restrict__ scale_W, const float* __restrict__ scale_b)
{
    int gid = blockIdx.x*blockDim.x + threadIdx.x;
    int b = gid >> 10, h = gid & 1023;
    const float4* a = (const float4*)(g_avg + b*EE);
    const float4* w = (const float4*)(scale_W + (size_t)h*EE);
    float s = 0.f;
    #pragma unroll 8
    for (int i=0;i<128;i++){
        float4 av=a[i], wv=w[i];
        s += av.x*wv.x + av.y*wv.y + av.z*wv.z + av.w*wv.w;
    }
    float v = fmaxf(s + scale_b[h], 0.f);
    g_h[gid] = v; g_c[gid] = v;
}

__global__ void attn_kernel(const float* __restrict__ attn_W, const int* __restrict__ src)
{
    int b = blockIdx.x, tid = threadIdx.x;
    __shared__ float sc[56];
    __shared__ float aw[56];
    int w = tid >> 5, lane = tid & 31;
    for (int s = w; s < SS; s += 8){
        const float* row = g_enc_out + (size_t)(b*SS+s)*EE;
        float a = 0.f;
        for (int e = lane; e < EE; e += 32) a += row[e]*attn_W[e];
        #pragma unroll
        for (int o=16;o>0;o>>=1) a += __shfl_xor_sync(0xffffffffu, a, o);
        if (lane==0) sc[s] = a;
    }
    __syncthreads();
    if (tid == 0){
        float mx = -1e30f;
        for (int s=0;s<SS;s++) mx = fmaxf(mx, sc[s]);
        float tot = 0.f;
        for (int s=0;s<SS;s++){
            float e = (src[b*SS+s]==0) ? 0.f : expf(sc[s]-mx);
            aw[s] = e; tot += e;
        }
        float inv = 1.f/tot;
        for (int s=0;s<SS;s++) aw[s] *= inv;
    }
    __syncthreads();
    for (int e = tid; e < EE; e += blockDim.x){
        float a = 0.f;
        #pragma unroll 5
        for (int s=0;s<SS;s++) a += aw[s]*g_enc_out[(size_t)(b*SS+s)*EE + e];
        g_ctx[b*EE + e] = a;
    }
}

__global__ void gconst_kernel(const float* __restrict__ W_ih,
                              const float* __restrict__ b_ih, const float* __restrict__ b_hh)
{
    int gid = blockIdx.x*blockDim.x + threadIdx.x;
    int b = gid >> 12, j = gid & 4095;
    const float4* c4 = (const float4*)(g_ctx + b*EE);
    const float4* w4 = (const float4*)(W_ih + (size_t)j*1024 + 512);
    float s = 0.f;
    #pragma unroll 8
    for (int i=0;i<128;i++){
        float4 cv=c4[i], wv=w4[i];
        s += cv.x*wv.x + cv.y*wv.y + cv.z*wv.z + cv.w*wv.w;
    }
    g_gconst[gid] = s + b_ih[j] + b_hh[j];
}

// ============================================================
// Hoisted token-embedding GEMM for ALL steps (fp32)
// ============================================================
__global__ __launch_bounds__(256)
void dec_pre(const int* __restrict__ tgt, const float* __restrict__ dec_emb,
             const float* __restrict__ W_ih)
{
    __shared__ __align__(16) float As[128*20];
    __shared__ __align__(16) float Bs[16*132];
    const int m0 = blockIdx.x * 128;
    const int n0 = blockIdx.y * 128;
    const int tid = threadIdx.x;
    const int tx = tid & 15, ty = tid >> 4;

    ull acc[8][2][2];
    #pragma unroll
    for (int i=0;i<8;i++)
        #pragma unroll
        for (int q=0;q<2;q++){ acc[i][q][0]=0ull; acc[i][q][1]=0ull; }

    for (int kt = 0; kt < 512; kt += 16){
        #pragma unroll
        for (int l=0;l<2;l++){
            int f4 = tid + 256*l;
            int row = f4 >> 2, k4 = (f4 & 3) << 2;
            int r = m0 + row;
            int tok = tgt[(r & 63)*50 + (r >> 6)];
            float4 v = *(const float4*)(dec_emb + (size_t)tok*512 + kt + k4);
            *(float4*)(As + row*20 + k4) = v;
        }
        #pragma unroll
        for (int l=0;l<2;l++){
            int f4 = tid + 256*l;
            int row = f4 >> 2, k4 = (f4 & 3) << 2;
            float4 v = *(const float4*)(W_ih + (size_t)(n0+row)*1024 + kt + k4);
            Bs[(k4+0)*132 + row] = v.x;
            Bs[(k4+1)*132 + row] = v.y;
            Bs[(k4+2)*132 + row] = v.z;
            Bs[(k4+3)*132 + row] = v.w;
        }
        __syncthreads();
        #pragma unroll
        for (int kq=0;kq<4;kq++){
            float4 av[8];
            #pragma unroll
            for (int i=0;i<8;i++) av[i] = *(const float4*)(As + (ty*8+i)*20 + kq*4);
            #pragma unroll
            for (int kk=0;kk<4;kk++){
                ull a2[8];
                #pragma unroll
                for (int i=0;i<8;i++){
                    float a = (kk==0)?av[i].x:(kk==1)?av[i].y:(kk==2)?av[i].z:av[i].w;
                    a2[i] = dup2(a);
                }
                const int k = kq*4+kk;
                #pragma unroll
                for (int q=0;q<2;q++){
                    ulonglong2 bv = *(const ulonglong2*)(Bs + k*132 + tx*4 + q*64);
                    #pragma unroll
                    for (int i=0;i<8;i++){ ffma2(acc[i][q][0], a2[i], bv.x);
                                           ffma2(acc[i][q][1], a2[i], bv.y); }
                }
            }
        }
        __syncthreads();
    }
    #pragma unroll
    for (int i=0;i<8;i++){
        int gm = m0 + ty*8 + i;
        int b = gm & 63;
        #pragma unroll
        for (int q=0;q<2;q++){
            int gn = n0 + tx*4 + q*64;
            float2 p0 = unpk(acc[i][q][0]);
            float2 p1 = unpk(acc[i][q][1]);
            float4 gc = *(const float4*)(g_gconst + (size_t)b*G4H + gn);
            *(float4*)(g_pre + (size_t)gm*G4H + gn) =
                make_float4(p0.x+gc.x, p0.y+gc.y, p1.x+gc.z, p1.y+gc.w);
        }
    }
}

// ============================================================
// PERSISTENT DATAFLOW decoder: all 49 steps, NO global barrier.
// 256 CTAs x 128 threads; CTA (ntile 0..31, ks 0..7).
// h-tile j (128 h values) is produced by the 32 CTAs with ntile%8==j
// (one gate-quarter each x 8 ksplits); consumed by CTAs with ks==j.
// Per-(step, h-tile) counters replace the grid barrier.
// LSTM: each CTA owns a disjoint 4h x 64b slice of its h-tile; c in regs.
// ============================================================
#define DSM_AS 0
#define DSM_BS (64*132)
#define DSM_TOT ((64*132 + 128*132)*4)

__global__ __launch_bounds__(128)
void decoder_df(const float* __restrict__ W_hh)
{
    extern __shared__ __align__(16) float dsm[];
    float* As = dsm + DSM_AS;
    float* Bs = dsm + DSM_BS;
    const int cid = blockIdx.x;
    const int ntile = cid & 31;
    const int ks = cid >> 5;
    const int n0 = ntile * 128;
    const int kbase = ks * KCHUNK;
    const int tid = threadIdx.x;
    const int tx = tid & 15, ty = tid >> 4;
    const int jown = ntile & 7;                 // h-tile this CTA's gates belong to
    const int slot = (ntile >> 3)*8 + ks;       // 0..31 within the h-tile's group

    // LSTM cell ownership: h = jown*128 + slot*4 + (tid&3); b in {tid>>2, tid>>2+32}
    const int hcell = jown*128 + slot*4 + (tid & 3);
    const int b0 = tid >> 2;
    const int b1 = b0 + 32;

    // one-time: W slice -> SMEM, transposed to Bs[k*132 + n]
    #pragma unroll 4
    for (int l = 0; l < 32; l++){
        int idx = tid + 128*l;
        int n = idx >> 5, k4 = (idx & 31) * 4;
        float4 v = *(const float4*)(W_hh + (size_t)(n0+n)*1024 + kbase + k4);
        Bs[(k4+0)*132 + n] = v.x;
        Bs[(k4+1)*132 + n] = v.y;
        Bs[(k4+2)*132 + n] = v.z;
        Bs[(k4+3)*132 + n] = v.w;
    }

    float c0 = g_c[b0*HH + hcell];
    float c1 = g_c[b1*HH + hcell];

    for (int t = 0; t < NSTEP; t++){
        // ---- wait for h-tile 'ks' from step t-1 (skip at t=0: h0 pre-written)
        if (t > 0){
            if (tid == 0){
                while (ldcg_i(&g_hcnt[t-1][ks]) < 32) __nanosleep(32);
                __threadfence();
            }
            __syncthreads();
        }

        // ---- stage h slice: As[m*132 + k] = g_h[m*1024 + kbase + k]
        #pragma unroll
        for (int l = 0; l < 16; l++){
            int idx = tid + 128*l;
            int m = idx >> 5, c4 = (idx & 31)*4;
            float4 v = __ldcg((const float4*)(g_h + m*1024 + kbase + c4));
            *(float4*)(As + m*132 + c4) = v;
        }
        __syncthreads();

        // ---- gates GEMM: 64m x 128n x 128k from SMEM
        ull acc[8][2][2];
        #pragma unroll
        for (int i=0;i<8;i++)
            #pragma unroll
            for (int q=0;q<2;q++){ acc[i][q][0]=0ull; acc[i][q][1]=0ull; }

        #pragma unroll 4
        for (int kq = 0; kq < 32; kq++){
            float4 av[8];
            #pragma unroll
            for (int i=0;i<8;i++) av[i] = *(const float4*)(As + (ty*8+i)*132 + kq*4);
            #pragma unroll
            for (int kk=0;kk<4;kk++){
                ull a2[8];
                #pragma unroll
                for (int i=0;i<8;i++){
                    float a = (kk==0)?av[i].x:(kk==1)?av[i].y:(kk==2)?av[i].z:av[i].w;
                    a2[i] = dup2(a);
                }
                const int k = kq*4+kk;
                #pragma unroll
                for (int q=0;q<2;q++){
                    ulonglong2 bv = *(const ulonglong2*)(Bs + k*132 + tx*4 + q*64);
                    #pragma unroll
                    for (int i=0;i<8;i++){ ffma2(acc[i][q][0], a2[i], bv.x);
                                           ffma2(acc[i][q][1], a2[i], bv.y); }
                }
            }
        }
        {
            float* outp = g_part + (size_t)ks*(BB*G4H);
            #pragma unroll
            for (int i=0;i<8;i++){
                int m = ty*8 + i;
                #pragma unroll
                for (int q=0;q<2;q++){
                    int n = n0 + tx*4 + q*64;
                    float2 p0 = unpk(acc[i][q][0]);
                    float2 p1 = unpk(acc[i][q][1]);
                    *(float4*)(outp + (size_t)m*G4H + n) =
                        make_float4(p0.x, p0.y, p1.x, p1.y);
                }
            }
        }
        __syncthreads();               // all partial stores issued (SMEM reuse + count order)
        if (tid == 0){
            __threadfence();           // partials visible before arrival
            atomicAdd(&g_gcnt[t][jown], 1);
            // ---- wait for all 32 gate contributions to h-tile jown
            while (ldcg_i(&g_gcnt[t][jown]) < 32) __nanosleep(32);
            __threadfence();
        }
        __syncthreads();

        // ---- LSTM for owned cells (2 per thread), c in registers
        #pragma unroll
        for (int e = 0; e < 2; e++){
            int b = (e==0) ? b0 : b1;
            size_t prow = (size_t)(t*64 + b)*G4H;
            float gi = g_pre[prow + hcell];
            float gf = g_pre[prow + 1024 + hcell];
            float gg = g_pre[prow + 2048 + hcell];
            float go = g_pre[prow + 3072 + hcell];
            int base = b*G4H;
            #pragma unroll
            for (int s=0;s<KSPLIT;s++){
                const float* p = g_part + (size_t)s*(BB*G4H) + base;
                gi += __ldcg(p + hcell);
                gf += __ldcg(p + 1024 + hcell);
                gg += __ldcg(p + 2048 + hcell);
                go += __ldcg(p + 3072 + hcell);
            }
            float c = (e==0) ? c0 : c1;
            float ii = 1.f/(1.f+expf(-gi));
            float ff = 1.f/(1.f+expf(-gf));
            float oo = 1.f/(1.f+expf(-go));
            float gt = tanhf(gg);
            float cn = ff*c + ii*gt;
            float hn = oo*tanhf(cn);
            if (e==0) c0 = cn; else c1 = cn;
            g_h[b*HH + hcell] = hn;
            g_Ah[(size_t)(t*64 + b)*KA + hcell] = __float2half_rn(hn);
        }
        __syncthreads();               // all h stores issued before arrival
        if (tid == 0){
            __threadfence();           // h visible before arrival
            atomicAdd(&g_hcnt[t][jown], 1);
        }
        // no global barrier: consumers of h-tile jown spin on g_hcnt
    }
}

// ============================================================
// Fallback per-step kernels (if residency check fails)
// ============================================================
__global__ __launch_bounds__(128)
void gates_gemm(const float* __restrict__ W_hh)
{
    __shared__ __align__(16) float As[64*20];
    __shared__ __align__(16) float Bs[16*132];
    const int n0 = blockIdx.x * 128;
    const int kbase = blockIdx.y * KCHUNK;
    const int tid = threadIdx.x;
    const int tx = tid & 15, ty = tid >> 4;

    ull acc[8][2][2];
    #pragma unroll
    for (int i=0;i<8;i++)
        #pragma unroll
        for (int q=0;q<2;q++){ acc[i][q][0]=0ull; acc[i][q][1]=0ull; }

    for (int kt = 0; kt < KCHUNK; kt += 16){
        const int kg0 = kbase + kt;
        #pragma unroll
        for (int l=0;l<2;l++){
            int f4 = tid + 128*l;
            int row = f4 >> 2, k4 = (f4 & 3) << 2;
            float4 v = *(const float4*)(g_h + row*1024 + kg0 + k4);
            *(float4*)(As + row*20 + k4) = v;
        }
        #pragma unroll
        for (int l=0;l<4;l++){
            int f4 = tid + 128*l;
            int row = f4 >> 2, k4 = (f4 & 3) << 2;
            float4 v = *(const float4*)(W_hh + (size_t)(n0+row)*1024 + kg0 + k4);
            Bs[(k4+0)*132 + row] = v.x;
            Bs[(k4+1)*132 + row] = v.y;
            Bs[(k4+2)*132 + row] = v.z;
            Bs[(k4+3)*132 + row] = v.w;
        }
        __syncthreads();
        #pragma unroll
        for (int kq=0;kq<4;kq++){
            float4 av[8];
            #pragma unroll
            for (int i=0;i<8;i++) av[i] = *(const float4*)(As + (ty*8+i)*20 + kq*4);
            #pragma unroll
            for (int kk=0;kk<4;kk++){
                ull a2[8];
                #pragma unroll
                for (int i=0;i<8;i++){
                    float a = (kk==0)?av[i].x:(kk==1)?av[i].y:(kk==2)?av[i].z:av[i].w;
                    a2[i] = dup2(a);
                }
                const int k = kq*4+kk;
                #pragma unroll
                for (int q=0;q<2;q++){
                    ulonglong2 bv = *(const ulonglong2*)(Bs + k*132 + tx*4 + q*64);
                    #pragma unroll
                    for (int i=0;i<8;i++){ ffma2(acc[i][q][0], a2[i], bv.x);
                                           ffma2(acc[i][q][1], a2[i], bv.y); }
                }
            }
        }
        __syncthreads();
    }
    float* outp = g_part + (size_t)blockIdx.y*(BB*G4H);
    #pragma unroll
    for (int i=0;i<8;i++){
        int m = ty*8 + i;
        #pragma unroll
        for (int q=0;q<2;q++){
            int n = n0 + tx*4 + q*64;
            float2 p0 = unpk(acc[i][q][0]);
            float2 p1 = unpk(acc[i][q][1]);
            *(float4*)(outp + (size_t)m*G4H + n) = make_float4(p0.x, p0.y, p1.x, p1.y);
        }
    }
}

__global__ void lstm_pw(int t)
{
    int gid = blockIdx.x*blockDim.x + threadIdx.x;
    int b = gid >> 10, h = gid & 1023;
    size_t prow = (size_t)(t*64 + b)*G4H;
    float gi = g_pre[prow + h];
    float gf = g_pre[prow + 1024 + h];
    float gg = g_pre[prow + 2048 + h];
    float go = g_pre[prow + 3072 + h];
    int base = b*G4H;
    #pragma unroll
    for (int s=0;s<KSPLIT;s++){
        const float* p = g_part + (size_t)s*(BB*G4H) + base;
        gi += p[h]; gf += p[1024+h]; gg += p[2048+h]; go += p[3072+h];
    }
    float c  = g_c[gid];
    float ii = 1.f/(1.f+expf(-gi));
    float ff = 1.f/(1.f+expf(-gf));
    float oo = 1.f/(1.f+expf(-go));
    float gt = tanhf(gg);
    float cn = ff*c + ii*gt;
    float hn = oo*tanhf(cn);
    g_c[gid] = cn; g_h[gid] = hn;
    g_Ah[(size_t)(t*64 + b)*KA + h] = __float2half_rn(hn);
}

// ============================================================
// proj_W fp32 -> fp16
// ============================================================
__global__ __launch_bounds__(256)
void conv_w(const float* __restrict__ W)
{
    size_t i = (size_t)blockIdx.x*blockDim.x + threadIdx.x;
    float4 v = ((const float4*)W)[i];
    __half h0 = __float2half_rn(v.x);
    __half h1 = __float2half_rn(v.y);
    __half h2 = __float2half_rn(v.z);
    __half h3 = __float2half_rn(v.w);
    ull packed;
    asm("mov.b64 %0, {%1,%2,%3,%4};" : "=l"(packed)
        : "h"(*(unsigned short*)&h0), "h"(*(unsigned short*)&h1),
          "h"(*(unsigned short*)&h2), "h"(*(unsigned short*)&h3));
    *(ull*)(g_Bh + i*4) = packed;
}

// ============================================================
// Projection via mma.sync fp16 (R8 config: CTA 128m x 256n)
// ============================================================
#define NSTG 4
#define TSTA 10240              /* 128 rows * 80 B */
#define TSTB 20480              /* 256 rows * 80 B */
#define SM_PROJ (NSTG*(TSTA+TSTB))  /* 122880 */
#define NKS (KA/32)             /* 32 k-chunks */

__global__ __launch_bounds__(256)
void proj_mma(float* __restrict__ out, const float* __restrict__ bias)
{
    extern __shared__ __align__(16) char sm[];
    const uint32_t uA = smem_u32(sm);
    const uint32_t uB = uA + NSTG*TSTA;
    const int tid = threadIdx.x;
    const int wid = tid >> 5, lane = tid & 31;
    const int m0 = blockIdx.x * 128;
    const int n0 = blockIdx.y * 256;
    const int wm = wid & 3, wn = wid >> 2;

    float acc[2][16][4];
    #pragma unroll
    for (int a=0;a<2;a++)
        #pragma unroll
        for (int j=0;j<16;j++)
            #pragma unroll
            for (int x=0;x<4;x++) acc[a][j][x] = 0.f;

    const __half* gA = g_Ah + (size_t)m0*KA;
    const __half* gB = g_Bh + (size_t)n0*KA;

    auto load_stage = [&](int slot, int ks){
        int k0 = ks * 32;
        uint32_t sA = uA + slot*TSTA;
        uint32_t sB = uB + slot*TSTB;
        #pragma unroll
        for (int i = 0; i < 2; i++){
            int idx = tid + 256*i;
            int row = idx >> 2, lc = idx & 3;
            cpasync16(sA + row*80 + lc*16, gA + (size_t)row*KA + k0 + lc*8);
        }
        #pragma unroll
        for (int i = 0; i < 4; i++){
            int idx = tid + 256*i;
            int row = idx >> 2, lc = idx & 3;
            cpasync16(sB + row*80 + lc*16, gB + (size_t)row*KA + k0 + lc*8);
        }
        cp_commit();
    };

    load_stage(0, 0);
    load_stage(1, 1);
    load_stage(2, 2);

    const int g  = lane >> 3;
    const int lr = lane & 7;

    for (int ks = 0; ks < NKS; ks++){
        asm volatile("cp.async.wait_group 2;");
        __syncthreads();
        int ld = ks + NSTG - 1;
        if (ld < NKS) load_stage(ld & (NSTG-1), ld);
        else cp_commit();

        const uint32_t bufA = uA + (ks & (NSTG-1))*TSTA;
        const uint32_t bufB = uB + (ks & (NSTG-1))*TSTB;

        #pragma unroll
        for (int kk = 0; kk < 32; kk += 16){
            uint32_t afr[2][4];
            #pragma unroll
            for (int mi = 0; mi < 2; mi++){
                int row = wm*32 + mi*16 + ((g & 1) ? 8 : 0) + lr;
                int kof = kk + (g >> 1)*8;
                ldm4(afr[mi], bufA + row*80 + kof*2);
            }
            uint32_t bfr[8][4];
            #pragma unroll
            for (int p = 0; p < 8; p++){
                int row = wn*128 + p*16 + (g >> 1)*8 + lr;
                int kof = kk + (g & 1)*8;
                ldm4(bfr[p], bufB + row*80 + kof*2);
            }
            #pragma unroll
            for (int mi = 0; mi < 2; mi++)
                #pragma unroll
                for (int j = 0; j < 16; j++){
                    int p = j >> 1, h2 = (j & 1)*2;
                    mma16816h(acc[mi][j], afr[mi], bfr[p][h2], bfr[p][h2+1]);
                }
        }
        __syncthreads();
    }

    // ---- epilogue ----
    const int tm = lane >> 2;
    const int tn = (lane & 3)*2;
    #pragma unroll
    for (int mi = 0; mi < 2; mi++){
        #pragma unroll
        for (int j = 0; j < 16; j++){
            int gn = n0 + wn*128 + j*8 + tn;
            float2 bb = *(const float2*)(bias + gn);
            int gm0 = m0 + wm*32 + mi*16 + tm;
            if (gm0 < MPROJ){
                float2 o; o.x = acc[mi][j][0] + bb.x; o.y = acc[mi][j][1] + bb.y;
                *(float2*)(out + (size_t)gm0*VTS + gn) = o;
            }
            int gm1 = gm0 + 8;
            if (gm1 < MPROJ){
                float2 o; o.x = acc[mi][j][2] + bb.x; o.y = acc[mi][j][3] + bb.y;
                *(float2*)(out + (size_t)gm1*VTS + gn) = o;
            }
        }
    }
}

// ============================================================
extern "C" void kernel_launch(void* const* d_in, const int* in_sizes, int n_in,
                              void* d_out, int out_size)
{
    const int*   src      = (const int*)  d_in[0];
    const int*   pos      = (const int*)  d_in[2];
    const int*   tgt      = (const int*)  d_in[3];
    const float* enc_emb  = (const float*)d_in[4];
    const float* pos_emb  = (const float*)d_in[5];
    const float* cat_W    = (const float*)d_in[6];
    const float* cat_b    = (const float*)d_in[7];
    const float* scale_W  = (const float*)d_in[8];
    const float* scale_b  = (const float*)d_in[9];
    const float* dec_emb  = (const float*)d_in[10];
    const float* attn_W   = (const float*)d_in[11];
    const float* W_ih     = (const float*)d_in[13];
    const float* W_hh     = (const float*)d_in[14];
    const float* b_ih     = (const float*)d_in[15];
    const float* b_hh     = (const float*)d_in[16];
    const float* proj_W   = (const float*)d_in[17];
    const float* proj_b   = (const float*)d_in[18];
    float* out = (float*)d_out;

    cudaFuncSetAttribute(proj_mma, cudaFuncAttributeMaxDynamicSharedMemorySize, SM_PROJ);
    cudaFuncSetAttribute(decoder_df, cudaFuncAttributeMaxDynamicSharedMemorySize, DSM_TOT);

    int per_sm = 0, n_sm = 0;
    cudaOccupancyMaxActiveBlocksPerMultiprocessor(&per_sm, decoder_df, 128, DSM_TOT);
    cudaDeviceGetAttribute(&n_sm, cudaDevAttrMultiProcessorCount, 0);
    const bool persistent_ok = ((long)per_sm * n_sm >= DCTA);

    // B conversion + flag reset (replay-safe)
    conv_w<<<32000, 256>>>(proj_W);
    reset_flags<<<2, 256>>>();

    // Encoder
    enc_gemm<<<dim3(25,4), 256>>>(src, pos, enc_emb, pos_emb, cat_W, cat_b);
    avg_kernel<<<64, 512>>>();
    h0_kernel<<<256, 256>>>(scale_W, scale_b);

    // Loop-invariant attention context + hoisted per-step constants
    attn_kernel<<<64, 256>>>(attn_W, src);
    gconst_kernel<<<1024, 256>>>(W_ih, b_ih, b_hh);
    dec_pre<<<dim3(25,32), 256>>>(tgt, dec_emb, W_ih);

    // Recurrence: dataflow-synchronized persistent decoder
    if (persistent_ok){
        decoder_df<<<DCTA, 128, DSM_TOT>>>(W_hh);
    } else {
        for (int t = 0; t < NSTEP; t++){
            gates_gemm<<<dim3(32, KSPLIT), 128>>>(W_hh);
            lstm_pw<<<256, 256>>>(t);
        }
    }

    // fp16 tensor-core projection (R8 config)
    proj_mma<<<dim3(25,125), 256, SM_PROJ>>>(out, proj_b);
}

// round 12
// speedup vs baseline: 1.3018x; 1.3018x over previous
#include <cuda_runtime.h>
#include <cuda_bf16.h>
#include <cuda_fp16.h>
#include <math.h>
#include <stdint.h>

#define BB 64
#define SS 50
#define EE 512
#define HH 1024
#define VTS 32000
#define NSTEP 49
#define MPROJ (NSTEP*BB)
#define MPAD  3200
#define G4H 4096
#define KSPLIT 8
#define KCHUNK 128
#define KA 1024
#define DCTA 256

typedef unsigned long long ull;

__device__ __forceinline__ ull dup2(float x){
    ull r; asm("mov.b64 %0, {%1, %1};" : "=l"(r) : "f"(x)); return r;
}
__device__ __forceinline__ void ffma2(ull &d, ull a, ull b){
    asm("fma.rn.f32x2 %0, %1, %2, %0;" : "+l"(d) : "l"(a), "l"(b));
}
__device__ __forceinline__ float2 unpk(ull v){
    float2 f; asm("mov.b64 {%0, %1}, %2;" : "=f"(f.x), "=f"(f.y) : "l"(v)); return f;
}
__device__ __forceinline__ uint32_t smem_u32(const void* p){
    uint32_t a;
    asm("{ .reg .u64 t; cvta.to.shared.u64 t, %1; cvt.u32.u64 %0, t; }" : "=r"(a) : "l"(p));
    return a;
}
__device__ __forceinline__ void cpasync16(uint32_t dst, const void* src){
    asm volatile("cp.async.cg.shared.global [%0], [%1], 16;" :: "r"(dst), "l"(src));
}
__device__ __forceinline__ void cp_commit(){
    asm volatile("cp.async.commit_group;");
}
__device__ __forceinline__ void ldm4(uint32_t* r, uint32_t a){
    asm volatile("ldmatrix.sync.aligned.m8n8.x4.shared.b16 {%0,%1,%2,%3}, [%4];"
        : "=r"(r[0]), "=r"(r[1]), "=r"(r[2]), "=r"(r[3]) : "r"(a));
}
__device__ __forceinline__ void mma16816h(float* c, const uint32_t* a, uint32_t b0, uint32_t b1){
    asm volatile("mma.sync.aligned.m16n8k16.row.col.f32.f16.f16.f32 "
        "{%0,%1,%2,%3}, {%4,%5,%6,%7}, {%8,%9}, {%0,%1,%2,%3};"
        : "+f"(c[0]), "+f"(c[1]), "+f"(c[2]), "+f"(c[3])
        : "r"(a[0]), "r"(a[1]), "r"(a[2]), "r"(a[3]), "r"(b0), "r"(b1));
}

__device__ float g_enc_out[BB*SS*EE];
__device__ float g_avg[BB*EE];
__device__ float g_ctx[BB*EE];
__device__ float g_h[BB*HH];
__device__ float g_c[BB*HH];
__device__ float g_part[KSPLIT*BB*G4H];
__device__ float g_pre[MPAD*G4H];
__device__ __half g_Ah[(size_t)MPAD*KA];
__device__ __half g_Bh[(size_t)VTS*KA];
__device__ __half g_Apre[(size_t)MPAD*KA];
__device__ __half g_Wih16[(size_t)G4H*KA];

__device__ unsigned g_bcount;
__device__ volatile unsigned g_bepoch;

__device__ __forceinline__ void gbar(unsigned &target){
    target += 1u;
    __syncthreads();
    if (threadIdx.x == 0){
        __threadfence();
        unsigned a = atomicAdd(&g_bcount, 1u);
        if (a == DCTA-1u){
            g_bcount = 0u;
            __threadfence();
            g_bepoch = g_bepoch + 1u;
        } else {
            while ((int)(g_bepoch - target) < 0) __nanosleep(64);
        }
    }
    __syncthreads();
}

__global__ __launch_bounds__(256)
void enc_gemm(const int* __restrict__ src, const int* __restrict__ pos,
              const float* __restrict__ enc_emb, const float* __restrict__ pos_emb,
              const float* __restrict__ cat_W, const float* __restrict__ cat_b)
{
    __shared__ __align__(16) float As[128*20];
    __shared__ __align__(16) float Bs[16*132];
    const int m0 = blockIdx.x * 128;
    const int n0 = blockIdx.y * 128;
    const int tid = threadIdx.x;
    const int tx = tid & 15, ty = tid >> 4;

    ull acc[8][2][2];
    #pragma unroll
    for (int i=0;i<8;i++)
        #pragma unroll
        for (int q=0;q<2;q++){ acc[i][q][0]=0ull; acc[i][q][1]=0ull; }

    for (int kt = 0; kt < 1024; kt += 16){
        #pragma unroll
        for (int l=0;l<2;l++){
            int f4 = tid + 256*l;
            int row = f4 >> 2, k4 = (f4 & 3) << 2;
            int kg = kt + k4;
            int r = m0 + row;
            float4 v;
            if (kg < 512) v = *(const float4*)(enc_emb + (size_t)src[r]*512 + kg);
            else          v = *(const float4*)(pos_emb + (size_t)pos[r]*512 + (kg - 512));
            *(float4*)(As + row*20 + k4) = v;
        }
        #pragma unroll
        for (int l=0;l<2;l++){
            int f4 = tid + 256*l;
            int row = f4 >> 2, k4 = (f4 & 3) << 2;
            float4 v = *(const float4*)(cat_W + (size_t)(n0+row)*1024 + kt + k4);
            Bs[(k4+0)*132 + row] = v.x;
            Bs[(k4+1)*132 + row] = v.y;
            Bs[(k4+2)*132 + row] = v.z;
            Bs[(k4+3)*132 + row] = v.w;
        }
        __syncthreads();
        #pragma unroll
        for (int kq=0;kq<4;kq++){
            float4 av[8];
            #pragma unroll
            for (int i=0;i<8;i++) av[i] = *(const float4*)(As + (ty*8+i)*20 + kq*4);
            #pragma unroll
            for (int kk=0;kk<4;kk++){
                ull a2[8];
                #pragma unroll
                for (int i=0;i<8;i++){
                    float a = (kk==0)?av[i].x:(kk==1)?av[i].y:(kk==2)?av[i].z:av[i].w;
                    a2[i] = dup2(a);
                }
                const int k = kq*4+kk;
                #pragma unroll
                for (int q=0;q<2;q++){
                    ulonglong2 bv = *(const ulonglong2*)(Bs + k*132 + tx*4 + q*64);
                    #pragma unroll
                    for (int i=0;i<8;i++){ ffma2(acc[i][q][0], a2[i], bv.x);
                                           ffma2(acc[i][q][1], a2[i], bv.y); }
                }
            }
        }
        __syncthreads();
    }
    #pragma unroll
    for (int i=0;i<8;i++){
        int gm = m0 + ty*8 + i;
        #pragma unroll
        for (int q=0;q<2;q++){
            int gn = n0 + tx*4 + q*64;
            float2 p0 = unpk(acc[i][q][0]);
            float2 p1 = unpk(acc[i][q][1]);
            float4 bb = *(const float4*)(cat_b + gn);
            *(float4*)(g_enc_out + (size_t)gm*512 + gn) =
                make_float4(p0.x+bb.x, p0.y+bb.y, p1.x+bb.z, p1.y+bb.w);
        }
    }
}

__global__ void avg_kernel()
{
    int b = blockIdx.x, e = threadIdx.x;
    float s = 0.f;
    #pragma unroll 5
    for (int si=0; si<SS; si++) s += g_enc_out[(b*SS+si)*EE + e];
    g_avg[b*EE + e] = s * (1.0f/50.0f);
}

__global__ __launch_bounds__(256)
void h0_kernel(const float* __restrict__ scale_W, const float* __restrict__ scale_b)
{
    int gw = blockIdx.x*8 + (threadIdx.x >> 5);
    int lane = threadIdx.x & 31;
    int b = gw >> 10, h = gw & 1023;
    const float* a = g_avg + b*EE;
    const float* w = scale_W + (size_t)h*EE;
    float s = 0.f;
    #pragma unroll
    for (int k = 0; k < 16; k++){
        int idx = k*32 + lane;
        s += a[idx] * w[idx];
    }
    #pragma unroll
    for (int o=16;o>0;o>>=1) s += __shfl_xor_sync(0xffffffffu, s, o);
    if (lane == 0){
        float v = fmaxf(s + scale_b[h], 0.f);
        g_h[b*HH + h] = v;
        g_c[b*HH + h] = v;
    }
}

__global__ void attn_kernel(const float* __restrict__ attn_W, const int* __restrict__ src)
{
    int b = blockIdx.x, tid = threadIdx.x;
    __shared__ float sc[56];
    __shared__ float aw[56];
    int w = tid >> 5, lane = tid & 31;
    for (int s = w; s < SS; s += 8){
        const float* row = g_enc_out + (size_t)(b*SS+s)*EE;
        float a = 0.f;
        for (int e = lane; e < EE; e += 32) a += row[e]*attn_W[e];
        #pragma unroll
        for (int o=16;o>0;o>>=1) a += __shfl_xor_sync(0xffffffffu, a, o);
        if (lane==0) sc[s] = a;
    }
    __syncthreads();
    if (tid == 0){
        float mx = -1e30f;
        for (int s=0;s<SS;s++) mx = fmaxf(mx, sc[s]);
        float tot = 0.f;
        for (int s=0;s<SS;s++){
            float e = (src[b*SS+s]==0) ? 0.f : expf(sc[s]-mx);
            aw[s] = e; tot += e;
        }
        float inv = 1.f/tot;
        for (int s=0;s<SS;s++) aw[s] *= inv;
    }
    __syncthreads();
    for (int e = tid; e < EE; e += blockDim.x){
        float a = 0.f;
        #pragma unroll 5
        for (int s=0;s<SS;s++) a += aw[s]*g_enc_out[(size_t)(b*SS+s)*EE + e];
        g_ctx[b*EE + e] = a;
    }
}

__global__ __launch_bounds__(256)
void build_apre(const int* __restrict__ tgt, const float* __restrict__ dec_emb)
{
    int r = blockIdx.x;
    int b = r & 63, t = r >> 6;
    int c = threadIdx.x * 4;
    const float* srcp;
    if (c < 512){
        int tok = tgt[b*50 + t];
        srcp = dec_emb + (size_t)tok*512 + c;
    } else {
        srcp = g_ctx + b*EE + (c - 512);
    }
    float4 v = *(const float4*)srcp;
    __half h0 = __float2half_rn(v.x);
    __half h1 = __float2half_rn(v.y);
    __half h2 = __float2half_rn(v.z);
    __half h3 = __float2half_rn(v.w);
    ull packed;
    asm("mov.b64 %0, {%1,%2,%3,%4};" : "=l"(packed)
        : "h"(*(unsigned short*)&h0), "h"(*(unsigned short*)&h1),
          "h"(*(unsigned short*)&h2), "h"(*(unsigned short*)&h3));
    *(ull*)(g_Apre + (size_t)r*KA + c) = packed;
}

__global__ __launch_bounds__(256)
void conv_wih(const float* __restrict__ W)
{
    size_t i = (size_t)blockIdx.x*blockDim.x + threadIdx.x;
    float4 v = ((const float4*)W)[i];
    __half h0 = __float2half_rn(v.x);
    __half h1 = __float2half_rn(v.y);
    __half h2 = __float2half_rn(v.z);
    __half h3 = __float2half_rn(v.w);
    ull packed;
    asm("mov.b64 %0, {%1,%2,%3,%4};" : "=l"(packed)
        : "h"(*(unsigned short*)&h0), "h"(*(unsigned short*)&h1),
          "h"(*(unsigned short*)&h2), "h"(*(unsigned short*)&h3));
    *(ull*)(g_Wih16 + i*4) = packed;
}

__global__ __launch_bounds__(256)
void conv_w(const float* __restrict__ W)
{
    size_t i = (size_t)blockIdx.x*blockDim.x + threadIdx.x;
    float4 v = ((const float4*)W)[i];
    __half h0 = __float2half_rn(v.x);
    __half h1 = __float2half_rn(v.y);
    __half h2 = __float2half_rn(v.z);
    __half h3 = __float2half_rn(v.w);
    ull packed;
    asm("mov.b64 %0, {%1,%2,%3,%4};" : "=l"(packed)
        : "h"(*(unsigned short*)&h0), "h"(*(unsigned short*)&h1),
          "h"(*(unsigned short*)&h2), "h"(*(unsigned short*)&h3));
    *(ull*)(g_Bh + i*4) = packed;
}

#define NSTG 4
#define TSTA 10240
#define TSTB 20480
#define SM_PROJ (NSTG*(TSTA+TSTB))
#define NKS (KA/32)

__global__ __launch_bounds__(256)
void pre_mma(const float* __restrict__ b_ih, const float* __restrict__ b_hh)
{
    extern __shared__ __align__(16) char sm[];
    const uint32_t uA = smem_u32(sm);
    const uint32_t uB = uA + NSTG*TSTA;
    const int tid = threadIdx.x;
    const int wid = tid >> 5, lane = tid & 31;
    const int m0 = blockIdx.x * 128;
    const int n0 = blockIdx.y * 256;
    const int wm = wid & 3, wn = wid >> 2;

    float acc[2][16][4];
    #pragma unroll
    for (int a=0;a<2;a++)
        #pragma unroll
        for (int j=0;j<16;j++)
            #pragma unroll
            for (int x=0;x<4;x++) acc[a][j][x] = 0.f;

    const __half* gA = g_Apre + (size_t)m0*KA;
    const __half* gB = g_Wih16 + (size_t)n0*KA;

    auto load_stage = [&](int slot, int ks){
        int k0 = ks * 32;
        uint32_t sA = uA + slot*TSTA;
        uint32_t sB = uB + slot*TSTB;
        #pragma unroll
        for (int i = 0; i < 2; i++){
            int idx = tid + 256*i;
            int row = idx >> 2, lc = idx & 3;
            cpasync16(sA + row*80 + lc*16, gA + (size_t)row*KA + k0 + lc*8);
        }
        #pragma unroll
        for (int i = 0; i < 4; i++){
            int idx = tid + 256*i;
            int row = idx >> 2, lc = idx & 3;
            cpasync16(sB + row*80 + lc*16, gB + (size_t)row*KA + k0 + lc*8);
        }
        cp_commit();
    };

    load_stage(0, 0);
    load_stage(1, 1);
    load_stage(2, 2);

    const int g  = lane >> 3;
    const int lr = lane & 7;

    for (int ks = 0; ks < NKS; ks++){
        asm volatile("cp.async.wait_group 2;");
        __syncthreads();
        int ld = ks + NSTG - 1;
        if (ld < NKS) load_stage(ld & (NSTG-1), ld);
        else cp_commit();

        const uint32_t bufA = uA + (ks & (NSTG-1))*TSTA;
        const uint32_t bufB = uB + (ks & (NSTG-1))*TSTB;

        #pragma unroll
        for (int kk = 0; kk < 32; kk += 16){
            uint32_t afr[2][4];
            #pragma unroll
            for (int mi = 0; mi < 2; mi++){
                int row = wm*32 + mi*16 + ((g & 1) ? 8 : 0) + lr;
                int kof = kk + (g >> 1)*8;
                ldm4(afr[mi], bufA + row*80 + kof*2);
            }
            uint32_t bfr[8][4];
            #pragma unroll
            for (int p = 0; p < 8; p++){
                int row = wn*128 + p*16 + (g >> 1)*8 + lr;
                int kof = kk + (g & 1)*8;
                ldm4(bfr[p], bufB + row*80 + kof*2);
            }
            #pragma unroll
            for (int mi = 0; mi < 2; mi++)
                #pragma unroll
                for (int j = 0; j < 16; j++){
                    int p = j >> 1, h2 = (j & 1)*2;
                    mma16816h(acc[mi][j], afr[mi], bfr[p][h2], bfr[p][h2+1]);
                }
        }
        __syncthreads();
    }

    const int tm = lane >> 2;
    const int tn = (lane & 3)*2;
    #pragma unroll
    for (int mi = 0; mi < 2; mi++){
        #pragma unroll
        for (int j = 0; j < 16; j++){
            int gn = n0 + wn*128 + j*8 + tn;
            float2 bi = *(const float2*)(b_ih + gn);
            float2 bh = *(const float2*)(b_hh + gn);
            float bx = bi.x + bh.x, by = bi.y + bh.y;
            int gm0 = m0 + wm*32 + mi*16 + tm;
            {
                float2 o; o.x = acc[mi][j][0] + bx; o.y = acc[mi][j][1] + by;
                *(float2*)(g_pre + (size_t)gm0*G4H + gn) = o;
            }
            int gm1 = gm0 + 8;
            {
                float2 o; o.x = acc[mi][j][2] + bx; o.y = acc[mi][j][3] + by;
                *(float2*)(g_pre + (size_t)gm1*G4H + gn) = o;
            }
        }
    }
}

#define DSM_AS 0
#define DSM_BS (64*132)
#define DSM_TOT ((64*132 + 128*132)*4)

__global__ __launch_bounds__(128)
void decoder_persist(const float* __restrict__ W_hh)
{
    extern __shared__ __align__(16) float dsm[];
    float* As = dsm + DSM_AS;
    float* Bs = dsm + DSM_BS;
    const int cid = blockIdx.x;
    const int n0 = (cid & 31) * 128;
    const int ksplit = cid >> 5;
    const int kbase = ksplit * KCHUNK;
    const int tid = threadIdx.x;
    const int tx = tid & 15, ty = tid >> 4;
    unsigned target = g_bepoch;

    #pragma unroll 4
    for (int l = 0; l < 32; l++){
        int idx = tid + 128*l;
        int n = idx >> 5, k4 = (idx & 31) * 4;
        float4 v = *(const float4*)(W_hh + (size_t)(n0+n)*1024 + kbase + k4);
        Bs[(k4+0)*132 + n] = v.x;
        Bs[(k4+1)*132 + n] = v.y;
        Bs[(k4+2)*132 + n] = v.z;
        Bs[(k4+3)*132 + n] = v.w;
    }

    const int gid0 = cid*128 + tid;
    const int gid1 = gid0 + 32768;
    float creg0 = g_c[gid0];
    float creg1 = g_c[gid1];

    for (int t = 0; t < NSTEP; t++){
        #pragma unroll
        for (int l = 0; l < 16; l++){
            int idx = tid + 128*l;
            int m = idx >> 5, c4 = (idx & 31)*4;
            float4 v = __ldcg((const float4*)(g_h + m*1024 + kbase + c4));
            *(float4*)(As + m*132 + c4) = v;
        }
        __syncthreads();

        ull acc[8][2][2];
        #pragma unroll
        for (int i=0;i<8;i++)
            #pragma unroll
            for (int q=0;q<2;q++){ acc[i][q][0]=0ull; acc[i][q][1]=0ull; }

        #pragma unroll 4
        for (int kq = 0; kq < 32; kq++){
            float4 av[8];
            #pragma unroll
            for (int i=0;i<8;i++) av[i] = *(const float4*)(As + (ty*8+i)*132 + kq*4);
            #pragma unroll
            for (int kk=0;kk<4;kk++){
                ull a2[8];
                #pragma unroll
                for (int i=0;i<8;i++){
                    float a = (kk==0)?av[i].x:(kk==1)?av[i].y:(kk==2)?av[i].z:av[i].w;
                    a2[i] = dup2(a);
                }
                const int k = kq*4+kk;
                #pragma unroll
                for (int q=0;q<2;q++){
                    ulonglong2 bv = *(const ulonglong2*)(Bs + k*132 + tx*4 + q*64);
                    #pragma unroll
                    for (int i=0;i<8;i++){ ffma2(acc[i][q][0], a2[i], bv.x);
                                           ffma2(acc[i][q][1], a2[i], bv.y); }
                }
            }
        }
        {
            float* outp = g_part + (size_t)ksplit*(BB*G4H);
            #pragma unroll
            for (int i=0;i<8;i++){
                int m = ty*8 + i;
                #pragma unroll
                for (int q=0;q<2;q++){
                    int n = n0 + tx*4 + q*64;
                    float2 p0 = unpk(acc[i][q][0]);
                    float2 p1 = unpk(acc[i][q][1]);
                    *(float4*)(outp + (size_t)m*G4H + n) =
                        make_float4(p0.x, p0.y, p1.x, p1.y);
                }
            }
        }
        __syncthreads();
        gbar(target);

        #pragma unroll
        for (int e = 0; e < 2; e++){
            int gid = (e==0) ? gid0 : gid1;
            int b = gid >> 10, h = gid & 1023;
            size_t prow = (size_t)(t*64 + b)*G4H;
            float gi = g_pre[prow + h];
            float gf = g_pre[prow + 1024 + h];
            float gg = g_pre[prow + 2048 + h];
            float go = g_pre[prow + 3072 + h];
            int base = b*G4H;
            #pragma unroll
            for (int s=0;s<KSPLIT;s++){
                const float* p = g_part + (size_t)s*(BB*G4H) + base;
                gi += __ldcg(p + h);
                gf += __ldcg(p + 1024 + h);
                gg += __ldcg(p + 2048 + h);
                go += __ldcg(p + 3072 + h);
            }
            float c = (e==0) ? creg0 : creg1;
            float ii = 1.f/(1.f+expf(-gi));
            float ff = 1.f/(1.f+expf(-gf));
            float oo = 1.f/(1.f+expf(-go));
            float gt = tanhf(gg);
            float cn = ff*c + ii*gt;
            float hn = oo*tanhf(cn);
            if (e==0) creg0 = cn; else creg1 = cn;
            g_h[gid] = hn;
            g_Ah[(size_t)(t*64 + b)*KA + h] = __float2half_rn(hn);
        }
        gbar(target);
    }
}

__global__ __launch_bounds__(128)
void gates_gemm(const float* __restrict__ W_hh)
{
    __shared__ __align__(16) float As[64*20];
    __shared__ __align__(16) float Bs[16*132];
    const int n0 = blockIdx.x * 128;
    const int kbase = blockIdx.y * KCHUNK;
    const int tid = threadIdx.x;
    const int tx = tid & 15, ty = tid >> 4;

    ull acc[8][2][2];
    #pragma unroll
    for (int i=0;i<8;i++)
        #pragma unroll
        for (int q=0;q<2;q++){ acc[i][q][0]=0ull; acc[i][q][1]=0ull; }

    for (int kt = 0; kt < KCHUNK; kt += 16){
        const int kg0 = kbase + kt;
        #pragma unroll
        for (int l=0;l<2;l++){
            int f4 = tid + 128*l;
            int row = f4 >> 2, k4 = (f4 & 3) << 2;
            float4 v = *(const float4*)(g_h + row*1024 + kg0 + k4);
            *(float4*)(As + row*20 + k4) = v;
        }
        #pragma unroll
        for (int l=0;l<4;l++){
            int f4 = tid + 128*l;
            int row = f4 >> 2, k4 = (f4 & 3) << 2;
            float4 v = *(const float4*)(W_hh + (size_t)(n0+row)*1024 + kg0 + k4);
            Bs[(k4+0)*132 + row] = v.x;
            Bs[(k4+1)*132 + row] = v.y;
            Bs[(k4+2)*132 + row] = v.z;
            Bs[(k4+3)*132 + row] = v.w;
        }
        __syncthreads();
        #pragma unroll
        for (int kq=0;kq<4;kq++){
            float4 av[8];
            #pragma unroll
            for (int i=0;i<8;i++) av[i] = *(const float4*)(As + (ty*8+i)*20 + kq*4);
            #pragma unroll
            for (int kk=0;kk<4;kk++){
                ull a2[8];
                #pragma unroll
                for (int i=0;i<8;i++){
                    float a = (kk==0)?av[i].x:(kk==1)?av[i].y:(kk==2)?av[i].z:av[i].w;
                    a2[i] = dup2(a);
                }
                const int k = kq*4+kk;
                #pragma unroll
                for (int q=0;q<2;q++){
                    ulonglong2 bv = *(const ulonglong2*)(Bs + k*132 + tx*4 + q*64);
                    #pragma unroll
                    for (int i=0;i<8;i++){ ffma2(acc[i][q][0], a2[i], bv.x);
                                           ffma2(acc[i][q][1], a2[i], bv.y); }
                }
            }
        }
        __syncthreads();
    }
    float* outp = g_part + (size_t)blockIdx.y*(BB*G4H);
    #pragma unroll
    for (int i=0;i<8;i++){
        int m = ty*8 + i;
        #pragma unroll
        for (int q=0;q<2;q++){
            int n = n0 + tx*4 + q*64;
            float2 p0 = unpk(acc[i][q][0]);
            float2 p1 = unpk(acc[i][q][1]);
            *(float4*)(outp + (size_t)m*G4H + n) = make_float4(p0.x, p0.y, p1.x, p1.y);
        }
    }
}

__global__ void lstm_pw(int t)
{
    int gid = blockIdx.x*blockDim.x + threadIdx.x;
    int b = gid >> 10, h = gid & 1023;
    size_t prow = (size_t)(t*64 + b)*G4H;
    float gi = g_pre[prow + h];
    float gf = g_pre[prow + 1024 + h];
    float gg = g_pre[prow + 2048 + h];
    float go = g_pre[prow + 3072 + h];
    int base = b*G4H;
    #pragma unroll
    for (int s=0;s<KSPLIT;s++){
        const float* p = g_part + (size_t)s*(BB*G4H) + base;
        gi += p[h]; gf += p[1024+h]; gg += p[2048+h]; go += p[3072+h];
    }
    float c  = g_c[gid];
    float ii = 1.f/(1.f+expf(-gi));
    float ff = 1.f/(1.f+expf(-gf));
    float oo = 1.f/(1.f+expf(-go));
    float gt = tanhf(gg);
    float cn = ff*c + ii*gt;
    float hn = oo*tanhf(cn);
    g_c[gid] = cn; g_h[gid] = hn;
    g_Ah[(size_t)(t*64 + b)*KA + h] = __float2half_rn(hn);
}

__global__ __launch_bounds__(256)
void proj_mma(float* __restrict__ out, const float* __restrict__ bias)
{
    extern __shared__ __align__(16) char sm[];
    const uint32_t uA = smem_u32(sm);
    const uint32_t uB = uA + NSTG*TSTA;
    const int tid = threadIdx.x;
    const int wid = tid >> 5, lane = tid & 31;
    const int m0 = blockIdx.x * 128;
    const int n0 = blockIdx.y * 256;
    const int wm = wid & 3, wn = wid >> 2;

    float acc[2][16][4];
    #pragma unroll
    for (int a=0;a<2;a++)
        #pragma unroll
        for (int j=0;j<16;j++)
            #pragma unroll
            for (int x=0;x<4;x++) acc[a][j][x] = 0.f;

    const __half* gA = g_Ah + (size_t)m0*KA;
    const __half* gB = g_Bh + (size_t)n0*KA;

    auto load_stage = [&](int slot, int ks){
        int k0 = ks * 32;
        uint32_t sA = uA + slot*TSTA;
        uint32_t sB = uB + slot*TSTB;
        #pragma unroll
        for (int i = 0; i < 2; i++){
            int idx = tid + 256*i;
            int row = idx >> 2, lc = idx & 3;
            cpasync16(sA + row*80 + lc*16, gA + (size_t)row*KA + k0 + lc*8);
        }
        #pragma unroll
        for (int i = 0; i < 4; i++){
            int idx = tid + 256*i;
            int row = idx >> 2, lc = idx & 3;
            cpasync16(sB + row*80 + lc*16, gB + (size_t)row*KA + k0 + lc*8);
        }
        cp_commit();
    };

    load_stage(0, 0);
    load_stage(1, 1);
    load_stage(2, 2);

    const int g  = lane >> 3;
    const int lr = lane & 7;

    for (int ks = 0; ks < NKS; ks++){
        asm volatile("cp.async.wait_group 2;");
        __syncthreads();
        int ld = ks + NSTG - 1;
        if (ld < NKS) load_stage(ld & (NSTG-1), ld);
        else cp_commit();

        const uint32_t bufA = uA + (ks & (NSTG-1))*TSTA;
        const uint32_t bufB = uB + (ks & (NSTG-1))*TSTB;

        #pragma unroll
        for (int kk = 0; kk < 32; kk += 16){
            uint32_t afr[2][4];
            #pragma unroll
            for (int mi = 0; mi < 2; mi++){
                int row = wm*32 + mi*16 + ((g & 1) ? 8 : 0) + lr;
                int kof = kk + (g >> 1)*8;
                ldm4(afr[mi], bufA + row*80 + kof*2);
            }
            uint32_t bfr[8][4];
            #pragma unroll
            for (int p = 0; p < 8; p++){
                int row = wn*128 + p*16 + (g >> 1)*8 + lr;
                int kof = kk + (g & 1)*8;
                ldm4(bfr[p], bufB + row*80 + kof*2);
            }
            #pragma unroll
            for (int mi = 0; mi < 2; mi++)
                #pragma unroll
                for (int j = 0; j < 16; j++){
                    int p = j >> 1, h2 = (j & 1)*2;
                    mma16816h(acc[mi][j], afr[mi], bfr[p][h2], bfr[p][h2+1]);
                }
        }
        __syncthreads();
    }

    const int tm = lane >> 2;
    const int tn = (lane & 3)*2;
    #pragma unroll
    for (int mi = 0; mi < 2; mi++){
        #pragma unroll
        for (int j = 0; j < 16; j++){
            int gn = n0 + wn*128 + j*8 + tn;
            float2 bb = *(const float2*)(bias + gn);
            int gm0 = m0 + wm*32 + mi*16 + tm;
            if (gm0 < MPROJ){
                float2 o; o.x = acc[mi][j][0] + bb.x; o.y = acc[mi][j][1] + bb.y;
                *(float2*)(out + (size_t)gm0*VTS + gn) = o;
            }
            int gm1 = gm0 + 8;
            if (gm1 < MPROJ){
                float2 o; o.x = acc[mi][j][2] + bb.x; o.y = acc[mi][j][3] + bb.y;
                *(float2*)(out + (size_t)gm1*VTS + gn) = o;
            }
        }
    }
}

extern "C" void kernel_launch(void* const* d_in, const int* in_sizes, int n_in,
                              void* d_out, int out_size)
{
    const int*   src      = (const int*)  d_in[0];
    const int*   pos      = (const int*)  d_in[2];
    const int*   tgt      = (const int*)  d_in[3];
    const float* enc_emb  = (const float*)d_in[4];
    const float* pos_emb  = (const float*)d_in[5];
    const float* cat_W    = (const float*)d_in[6];
    const float* cat_b    = (const float*)d_in[7];
    const float* scale_W  = (const float*)d_in[8];
    const float* scale_b  = (const float*)d_in[9];
    const float* dec_emb  = (const float*)d_in[10];
    const float* attn_W   = (const float*)d_in[11];
    const float* W_ih     = (const float*)d_in[13];
    const float* W_hh     = (const float*)d_in[14];
    const float* b_ih     = (const float*)d_in[15];
    const float* b_hh     = (const float*)d_in[16];
    const float* proj_W   = (const float*)d_in[17];
    const float* proj_b   = (const float*)d_in[18];
    float* out = (float*)d_out;

    cudaFuncSetAttribute(proj_mma, cudaFuncAttributeMaxDynamicSharedMemorySize, SM_PROJ);
    cudaFuncSetAttribute(pre_mma, cudaFuncAttributeMaxDynamicSharedMemorySize, SM_PROJ);
    cudaFuncSetAttribute(decoder_persist, cudaFuncAttributeMaxDynamicSharedMemorySize, DSM_TOT);

    int per_sm = 0, n_sm = 0;
    cudaOccupancyMaxActiveBlocksPerMultiprocessor(&per_sm, decoder_persist, 128, DSM_TOT);
    cudaDeviceGetAttribute(&n_sm, cudaDevAttrMultiProcessorCount, 0);
    const bool persistent_ok = ((long)per_sm * n_sm >= DCTA);

    // Weight conversions
    conv_w<<<32000, 256>>>(proj_W);
    conv_wih<<<4096, 256>>>(W_ih);

    // Encoder
    enc_gemm<<<dim3(25,4), 256>>>(src, pos, enc_emb, pos_emb, cat_W, cat_b);
    avg_kernel<<<64, 512>>>();
    h0_kernel<<<8192, 256>>>(scale_W, scale_b);

    // Loop-invariant attention context + fused fp16 pre-GEMM
    attn_kernel<<<64, 256>>>(attn_W, src);
    build_apre<<<3200, 256>>>(tgt, dec_emb);
    pre_mma<<<dim3(25,16), 256, SM_PROJ>>>(b_ih, b_hh);

    // Recurrence
    if (persistent_ok){
        decoder_persist<<<DCTA, 128, DSM_TOT>>>(W_hh);
    } else {
        for (int t = 0; t < NSTEP; t++){
            gates_gemm<<<dim3(32, KSPLIT), 128>>>(W_hh);
            lstm_pw<<<256, 256>>>(t);
        }
    }

    // fp16 tensor-core projection
    proj_mma<<<dim3(25,125), 256, SM_PROJ>>>(out, proj_b);
}

// round 13
// speedup vs baseline: 1.6927x; 1.3002x over previous
#include <cuda_runtime.h>
#include <cuda_bf16.h>
#include <cuda_fp16.h>
#include <math.h>
#include <stdint.h>

#define BB 64
#define SS 50
#define EE 512
#define HH 1024
#define VTS 32000
#define NSTEP 49
#define MPROJ (NSTEP*BB)
#define MPAD  3200
#define G4H 4096
#define KSPLIT 8
#define KCHUNK 128
#define KA 1024
#define DCTA 256

typedef unsigned long long ull;

__device__ __forceinline__ ull dup2(float x){
    ull r; asm("mov.b64 %0, {%1, %1};" : "=l"(r) : "f"(x)); return r;
}
__device__ __forceinline__ void ffma2(ull &d, ull a, ull b){
    asm("fma.rn.f32x2 %0, %1, %2, %0;" : "+l"(d) : "l"(a), "l"(b));
}
__device__ __forceinline__ float2 unpk(ull v){
    float2 f; asm("mov.b64 {%0, %1}, %2;" : "=f"(f.x), "=f"(f.y) : "l"(v)); return f;
}
__device__ __forceinline__ uint32_t smem_u32(const void* p){
    uint32_t a;
    asm("{ .reg .u64 t; cvta.to.shared.u64 t, %1; cvt.u32.u64 %0, t; }" : "=r"(a) : "l"(p));
    return a;
}
__device__ __forceinline__ void cpasync16(uint32_t dst, const void* src){
    asm volatile("cp.async.cg.shared.global [%0], [%1], 16;" :: "r"(dst), "l"(src));
}
__device__ __forceinline__ void cp_commit(){
    asm volatile("cp.async.commit_group;");
}
__device__ __forceinline__ void ldm4(uint32_t* r, uint32_t a){
    asm volatile("ldmatrix.sync.aligned.m8n8.x4.shared.b16 {%0,%1,%2,%3}, [%4];"
        : "=r"(r[0]), "=r"(r[1]), "=r"(r[2]), "=r"(r[3]) : "r"(a));
}
__device__ __forceinline__ void mma16816h(float* c, const uint32_t* a, uint32_t b0, uint32_t b1){
    asm volatile("mma.sync.aligned.m16n8k16.row.col.f32.f16.f16.f32 "
        "{%0,%1,%2,%3}, {%4,%5,%6,%7}, {%8,%9}, {%0,%1,%2,%3};"
        : "+f"(c[0]), "+f"(c[1]), "+f"(c[2]), "+f"(c[3])
        : "r"(a[0]), "r"(a[1]), "r"(a[2]), "r"(a[3]), "r"(b0), "r"(b1));
}

__device__ float g_enc_out[BB*SS*EE];
__device__ float g_avg[BB*EE];
__device__ float g_ctx[BB*EE];
__device__ float g_h[BB*HH];
__device__ float g_c[BB*HH];
__device__ float g_part[KSPLIT*BB*G4H];
__device__ float g_pre[MPAD*G4H];
__device__ __half g_h16[BB*HH];              // fp16 hidden state (current step)
__device__ __half g_Ah[(size_t)MPAD*KA];
__device__ __half g_Bh[(size_t)VTS*KA];
__device__ __half g_Apre[(size_t)MPAD*KA];
__device__ __half g_Wih16[(size_t)G4H*KA];
__device__ __half g_Whh16[(size_t)G4H*KA];   // fp16 W_hh

__device__ unsigned g_bcount;
__device__ volatile unsigned g_bepoch;

__device__ __forceinline__ void gbar(unsigned &target){
    target += 1u;
    __syncthreads();
    if (threadIdx.x == 0){
        __threadfence();
        unsigned a = atomicAdd(&g_bcount, 1u);
        if (a == DCTA-1u){
            g_bcount = 0u;
            __threadfence();
            g_bepoch = g_bepoch + 1u;
        } else {
            while ((int)(g_bepoch - target) < 0) __nanosleep(64);
        }
    }
    __syncthreads();
}

// ============================================================
// Encoder GEMM (fp32 FFMA2)
// ============================================================
__global__ __launch_bounds__(256)
void enc_gemm(const int* __restrict__ src, const int* __restrict__ pos,
              const float* __restrict__ enc_emb, const float* __restrict__ pos_emb,
              const float* __restrict__ cat_W, const float* __restrict__ cat_b)
{
    __shared__ __align__(16) float As[128*20];
    __shared__ __align__(16) float Bs[16*132];
    const int m0 = blockIdx.x * 128;
    const int n0 = blockIdx.y * 128;
    const int tid = threadIdx.x;
    const int tx = tid & 15, ty = tid >> 4;

    ull acc[8][2][2];
    #pragma unroll
    for (int i=0;i<8;i++)
        #pragma unroll
        for (int q=0;q<2;q++){ acc[i][q][0]=0ull; acc[i][q][1]=0ull; }

    for (int kt = 0; kt < 1024; kt += 16){
        #pragma unroll
        for (int l=0;l<2;l++){
            int f4 = tid + 256*l;
            int row = f4 >> 2, k4 = (f4 & 3) << 2;
            int kg = kt + k4;
            int r = m0 + row;
            float4 v;
            if (kg < 512) v = *(const float4*)(enc_emb + (size_t)src[r]*512 + kg);
            else          v = *(const float4*)(pos_emb + (size_t)pos[r]*512 + (kg - 512));
            *(float4*)(As + row*20 + k4) = v;
        }
        #pragma unroll
        for (int l=0;l<2;l++){
            int f4 = tid + 256*l;
            int row = f4 >> 2, k4 = (f4 & 3) << 2;
            float4 v = *(const float4*)(cat_W + (size_t)(n0+row)*1024 + kt + k4);
            Bs[(k4+0)*132 + row] = v.x;
            Bs[(k4+1)*132 + row] = v.y;
            Bs[(k4+2)*132 + row] = v.z;
            Bs[(k4+3)*132 + row] = v.w;
        }
        __syncthreads();
        #pragma unroll
        for (int kq=0;kq<4;kq++){
            float4 av[8];
            #pragma unroll
            for (int i=0;i<8;i++) av[i] = *(const float4*)(As + (ty*8+i)*20 + kq*4);
            #pragma unroll
            for (int kk=0;kk<4;kk++){
                ull a2[8];
                #pragma unroll
                for (int i=0;i<8;i++){
                    float a = (kk==0)?av[i].x:(kk==1)?av[i].y:(kk==2)?av[i].z:av[i].w;
                    a2[i] = dup2(a);
                }
                const int k = kq*4+kk;
                #pragma unroll
                for (int q=0;q<2;q++){
                    ulonglong2 bv = *(const ulonglong2*)(Bs + k*132 + tx*4 + q*64);
                    #pragma unroll
                    for (int i=0;i<8;i++){ ffma2(acc[i][q][0], a2[i], bv.x);
                                           ffma2(acc[i][q][1], a2[i], bv.y); }
                }
            }
        }
        __syncthreads();
    }
    #pragma unroll
    for (int i=0;i<8;i++){
        int gm = m0 + ty*8 + i;
        #pragma unroll
        for (int q=0;q<2;q++){
            int gn = n0 + tx*4 + q*64;
            float2 p0 = unpk(acc[i][q][0]);
            float2 p1 = unpk(acc[i][q][1]);
            float4 bb = *(const float4*)(cat_b + gn);
            *(float4*)(g_enc_out + (size_t)gm*512 + gn) =
                make_float4(p0.x+bb.x, p0.y+bb.y, p1.x+bb.z, p1.y+bb.w);
        }
    }
}

__global__ void avg_kernel()
{
    int b = blockIdx.x, e = threadIdx.x;
    float s = 0.f;
    #pragma unroll 5
    for (int si=0; si<SS; si++) s += g_enc_out[(b*SS+si)*EE + e];
    g_avg[b*EE + e] = s * (1.0f/50.0f);
}

__global__ __launch_bounds__(256)
void h0_kernel(const float* __restrict__ scale_W, const float* __restrict__ scale_b)
{
    int gw = blockIdx.x*8 + (threadIdx.x >> 5);
    int lane = threadIdx.x & 31;
    int b = gw >> 10, h = gw & 1023;
    const float* a = g_avg + b*EE;
    const float* w = scale_W + (size_t)h*EE;
    float s = 0.f;
    #pragma unroll
    for (int k = 0; k < 16; k++){
        int idx = k*32 + lane;
        s += a[idx] * w[idx];
    }
    #pragma unroll
    for (int o=16;o>0;o>>=1) s += __shfl_xor_sync(0xffffffffu, s, o);
    if (lane == 0){
        float v = fmaxf(s + scale_b[h], 0.f);
        g_h[b*HH + h] = v;
        g_c[b*HH + h] = v;
        g_h16[b*HH + h] = __float2half_rn(v);
    }
}

__global__ void attn_kernel(const float* __restrict__ attn_W, const int* __restrict__ src)
{
    int b = blockIdx.x, tid = threadIdx.x;
    __shared__ float sc[56];
    __shared__ float aw[56];
    int w = tid >> 5, lane = tid & 31;
    for (int s = w; s < SS; s += 8){
        const float* row = g_enc_out + (size_t)(b*SS+s)*EE;
        float a = 0.f;
        for (int e = lane; e < EE; e += 32) a += row[e]*attn_W[e];
        #pragma unroll
        for (int o=16;o>0;o>>=1) a += __shfl_xor_sync(0xffffffffu, a, o);
        if (lane==0) sc[s] = a;
    }
    __syncthreads();
    if (tid == 0){
        float mx = -1e30f;
        for (int s=0;s<SS;s++) mx = fmaxf(mx, sc[s]);
        float tot = 0.f;
        for (int s=0;s<SS;s++){
            float e = (src[b*SS+s]==0) ? 0.f : expf(sc[s]-mx);
            aw[s] = e; tot += e;
        }
        float inv = 1.f/tot;
        for (int s=0;s<SS;s++) aw[s] *= inv;
    }
    __syncthreads();
    for (int e = tid; e < EE; e += blockDim.x){
        float a = 0.f;
        #pragma unroll 5
        for (int s=0;s<SS;s++) a += aw[s]*g_enc_out[(size_t)(b*SS+s)*EE + e];
        g_ctx[b*EE + e] = a;
    }
}

__global__ __launch_bounds__(256)
void build_apre(const int* __restrict__ tgt, const float* __restrict__ dec_emb)
{
    int r = blockIdx.x;
    int b = r & 63, t = r >> 6;
    int c = threadIdx.x * 4;
    const float* srcp;
    if (c < 512){
        int tok = tgt[b*50 + t];
        srcp = dec_emb + (size_t)tok*512 + c;
    } else {
        srcp = g_ctx + b*EE + (c - 512);
    }
    float4 v = *(const float4*)srcp;
    __half h0 = __float2half_rn(v.x);
    __half h1 = __float2half_rn(v.y);
    __half h2 = __float2half_rn(v.z);
    __half h3 = __float2half_rn(v.w);
    ull packed;
    asm("mov.b64 %0, {%1,%2,%3,%4};" : "=l"(packed)
        : "h"(*(unsigned short*)&h0), "h"(*(unsigned short*)&h1),
          "h"(*(unsigned short*)&h2), "h"(*(unsigned short*)&h3));
    *(ull*)(g_Apre + (size_t)r*KA + c) = packed;
}

__global__ __launch_bounds__(256)
void conv_wih(const float* __restrict__ W)
{
    size_t i = (size_t)blockIdx.x*blockDim.x + threadIdx.x;
    float4 v = ((const float4*)W)[i];
    __half h0 = __float2half_rn(v.x);
    __half h1 = __float2half_rn(v.y);
    __half h2 = __float2half_rn(v.z);
    __half h3 = __float2half_rn(v.w);
    ull packed;
    asm("mov.b64 %0, {%1,%2,%3,%4};" : "=l"(packed)
        : "h"(*(unsigned short*)&h0), "h"(*(unsigned short*)&h1),
          "h"(*(unsigned short*)&h2), "h"(*(unsigned short*)&h3));
    *(ull*)(g_Wih16 + i*4) = packed;
}

__global__ __launch_bounds__(256)
void conv_whh(const float* __restrict__ W)
{
    size_t i = (size_t)blockIdx.x*blockDim.x + threadIdx.x;
    float4 v = ((const float4*)W)[i];
    __half h0 = __float2half_rn(v.x);
    __half h1 = __float2half_rn(v.y);
    __half h2 = __float2half_rn(v.z);
    __half h3 = __float2half_rn(v.w);
    ull packed;
    asm("mov.b64 %0, {%1,%2,%3,%4};" : "=l"(packed)
        : "h"(*(unsigned short*)&h0), "h"(*(unsigned short*)&h1),
          "h"(*(unsigned short*)&h2), "h"(*(unsigned short*)&h3));
    *(ull*)(g_Whh16 + i*4) = packed;
}

__global__ __launch_bounds__(256)
void conv_w(const float* __restrict__ W)
{
    size_t i = (size_t)blockIdx.x*blockDim.x + threadIdx.x;
    float4 v = ((const float4*)W)[i];
    __half h0 = __float2half_rn(v.x);
    __half h1 = __float2half_rn(v.y);
    __half h2 = __float2half_rn(v.z);
    __half h3 = __float2half_rn(v.w);
    ull packed;
    asm("mov.b64 %0, {%1,%2,%3,%4};" : "=l"(packed)
        : "h"(*(unsigned short*)&h0), "h"(*(unsigned short*)&h1),
          "h"(*(unsigned short*)&h2), "h"(*(unsigned short*)&h3));
    *(ull*)(g_Bh + i*4) = packed;
}

#define NSTG 4
#define TSTA 10240
#define TSTB 20480
#define SM_PROJ (NSTG*(TSTA+TSTB))
#define NKS (KA/32)

// ============================================================
// pre-GEMM (fp16 mma): g_pre = A_pre . W_ih^T + b_ih + b_hh
// ============================================================
__global__ __launch_bounds__(256)
void pre_mma(const float* __restrict__ b_ih, const float* __restrict__ b_hh)
{
    extern __shared__ __align__(16) char sm[];
    const uint32_t uA = smem_u32(sm);
    const uint32_t uB = uA + NSTG*TSTA;
    const int tid = threadIdx.x;
    const int wid = tid >> 5, lane = tid & 31;
    const int m0 = blockIdx.x * 128;
    const int n0 = blockIdx.y * 256;
    const int wm = wid & 3, wn = wid >> 2;

    float acc[2][16][4];
    #pragma unroll
    for (int a=0;a<2;a++)
        #pragma unroll
        for (int j=0;j<16;j++)
            #pragma unroll
            for (int x=0;x<4;x++) acc[a][j][x] = 0.f;

    const __half* gA = g_Apre + (size_t)m0*KA;
    const __half* gB = g_Wih16 + (size_t)n0*KA;

    auto load_stage = [&](int slot, int ks){
        int k0 = ks * 32;
        uint32_t sA = uA + slot*TSTA;
        uint32_t sB = uB + slot*TSTB;
        #pragma unroll
        for (int i = 0; i < 2; i++){
            int idx = tid + 256*i;
            int row = idx >> 2, lc = idx & 3;
            cpasync16(sA + row*80 + lc*16, gA + (size_t)row*KA + k0 + lc*8);
        }
        #pragma unroll
        for (int i = 0; i < 4; i++){
            int idx = tid + 256*i;
            int row = idx >> 2, lc = idx & 3;
            cpasync16(sB + row*80 + lc*16, gB + (size_t)row*KA + k0 + lc*8);
        }
        cp_commit();
    };

    load_stage(0, 0);
    load_stage(1, 1);
    load_stage(2, 2);

    const int g  = lane >> 3;
    const int lr = lane & 7;

    for (int ks = 0; ks < NKS; ks++){
        asm volatile("cp.async.wait_group 2;");
        __syncthreads();
        int ld = ks + NSTG - 1;
        if (ld < NKS) load_stage(ld & (NSTG-1), ld);
        else cp_commit();

        const uint32_t bufA = uA + (ks & (NSTG-1))*TSTA;
        const uint32_t bufB = uB + (ks & (NSTG-1))*TSTB;

        #pragma unroll
        for (int kk = 0; kk < 32; kk += 16){
            uint32_t afr[2][4];
            #pragma unroll
            for (int mi = 0; mi < 2; mi++){
                int row = wm*32 + mi*16 + ((g & 1) ? 8 : 0) + lr;
                int kof = kk + (g >> 1)*8;
                ldm4(afr[mi], bufA + row*80 + kof*2);
            }
            uint32_t bfr[8][4];
            #pragma unroll
            for (int p = 0; p < 8; p++){
                int row = wn*128 + p*16 + (g >> 1)*8 + lr;
                int kof = kk + (g & 1)*8;
                ldm4(bfr[p], bufB + row*80 + kof*2);
            }
            #pragma unroll
            for (int mi = 0; mi < 2; mi++)
                #pragma unroll
                for (int j = 0; j < 16; j++){
                    int p = j >> 1, h2 = (j & 1)*2;
                    mma16816h(acc[mi][j], afr[mi], bfr[p][h2], bfr[p][h2+1]);
                }
        }
        __syncthreads();
    }

    const int tm = lane >> 2;
    const int tn = (lane & 3)*2;
    #pragma unroll
    for (int mi = 0; mi < 2; mi++){
        #pragma unroll
        for (int j = 0; j < 16; j++){
            int gn = n0 + wn*128 + j*8 + tn;
            float2 bi = *(const float2*)(b_ih + gn);
            float2 bh = *(const float2*)(b_hh + gn);
            float bx = bi.x + bh.x, by = bi.y + bh.y;
            int gm0 = m0 + wm*32 + mi*16 + tm;
            {
                float2 o; o.x = acc[mi][j][0] + bx; o.y = acc[mi][j][1] + by;
                *(float2*)(g_pre + (size_t)gm0*G4H + gn) = o;
            }
            int gm1 = gm0 + 8;
            {
                float2 o; o.x = acc[mi][j][2] + bx; o.y = acc[mi][j][3] + by;
                *(float2*)(g_pre + (size_t)gm1*G4H + gn) = o;
            }
        }
    }
}

// ============================================================
// PERSISTENT decoder with fp16 tensor-core recurrent GEMM.
// 256 CTAs x 128 threads; CTA (ntile 0..31, ks 0..7).
// SMEM: Bs = W_hh fp16 slice 128n x 128k (pitch 272B, loaded once),
//       As = h fp16 slice 64m x 128k (pitch 272B, staged per step).
// 4 warps: warp w owns M rows [w*16, w*16+16), full N=128.
// ============================================================
#define DPITCH 272                         /* 128 fp16 + 8 pad */
#define DSM_AS 0                           /* 64 * 272 = 17408 */
#define DSM_BS (64*DPITCH)
#define DSM_TOT (DSM_BS + 128*DPITCH)      /* 17408 + 34816 = 52224 */

__global__ __launch_bounds__(128)
void decoder_tc(void)
{
    extern __shared__ __align__(16) char dsm[];
    const uint32_t uAs = smem_u32(dsm) + DSM_AS;
    const uint32_t uBs = smem_u32(dsm) + DSM_BS;
    const int cid = blockIdx.x;
    const int ntile = cid & 31;
    const int ksplit = cid >> 5;
    const int n0 = ntile * 128;
    const int kbase = ksplit * KCHUNK;
    const int tid = threadIdx.x;
    const int wid = tid >> 5, lane = tid & 31;
    unsigned target = g_bepoch;

    // one-time: W_hh fp16 slice -> SMEM (row-major n x k, pitch 272B)
    #pragma unroll
    for (int l = 0; l < 16; l++){
        int idx = tid + 128*l;              // 2048 16B chunks
        int n = idx >> 4, kc = (idx & 15)*8;
        uint4 v = *(const uint4*)(g_Whh16 + (size_t)(n0+n)*KA + kbase + kc);
        *(uint4*)(dsm + DSM_BS + n*DPITCH + kc*2) = v;
    }

    const int gid0 = cid*128 + tid;
    const int gid1 = gid0 + 32768;
    float creg0 = g_c[gid0];
    float creg1 = g_c[gid1];

    const int g  = lane >> 3;
    const int lr = lane & 7;
    const int tm = lane >> 2;
    const int tn = (lane & 3)*2;

    for (int t = 0; t < NSTEP; t++){
        // ---- stage h fp16 slice: As[m][k] = g_h16[m*1024 + kbase + k]
        #pragma unroll
        for (int l = 0; l < 8; l++){
            int idx = tid + 128*l;          // 1024 16B chunks
            int m = idx >> 4, kc = (idx & 15)*8;
            uint4 v = __ldcg((const uint4*)(g_h16 + m*HH + kbase + kc));
            *(uint4*)(dsm + DSM_AS + m*DPITCH + kc*2) = v;
        }
        __syncthreads();

        // ---- recurrent GEMM via mma.sync: M64 x N128 x K128
        float acc[16][4];
        #pragma unroll
        for (int j=0;j<16;j++)
            #pragma unroll
            for (int x=0;x<4;x++) acc[j][x] = 0.f;

        #pragma unroll
        for (int kk = 0; kk < 128; kk += 16){
            uint32_t afr[4];
            {
                int row = wid*16 + ((g & 1) ? 8 : 0) + lr;
                int kof = kk + (g >> 1)*8;
                ldm4(afr, uAs + row*DPITCH + kof*2);
            }
            uint32_t bfr[8][4];
            #pragma unroll
            for (int p = 0; p < 8; p++){
                int row = p*16 + (g >> 1)*8 + lr;
                int kof = kk + (g & 1)*8;
                ldm4(bfr[p], uBs + row*DPITCH + kof*2);
            }
            #pragma unroll
            for (int j = 0; j < 16; j++){
                int p = j >> 1, h2 = (j & 1)*2;
                mma16816h(acc[j], afr, bfr[p][h2], bfr[p][h2+1]);
            }
        }

        // ---- store partials: g_part[ks][m][n0+n]
        {
            float* outp = g_part + (size_t)ksplit*(BB*G4H);
            #pragma unroll
            for (int j = 0; j < 16; j++){
                int n = n0 + j*8 + tn;
                int m0r = wid*16 + tm;
                *(float2*)(outp + (size_t)m0r*G4H + n) =
                    make_float2(acc[j][0], acc[j][1]);
                *(float2*)(outp + (size_t)(m0r+8)*G4H + n) =
                    make_float2(acc[j][2], acc[j][3]);
            }
        }
        __syncthreads();
        gbar(target);

        // ---- LSTM pointwise: 2 cells per thread
        #pragma unroll
        for (int e = 0; e < 2; e++){
            int gid = (e==0) ? gid0 : gid1;
            int b = gid >> 10, h = gid & 1023;
            size_t prow = (size_t)(t*64 + b)*G4H;
            float gi = g_pre[prow + h];
            float gf = g_pre[prow + 1024 + h];
            float gg = g_pre[prow + 2048 + h];
            float go = g_pre[prow + 3072 + h];
            int base = b*G4H;
            #pragma unroll
            for (int s=0;s<KSPLIT;s++){
                const float* p = g_part + (size_t)s*(BB*G4H) + base;
                gi += __ldcg(p + h);
                gf += __ldcg(p + 1024 + h);
                gg += __ldcg(p + 2048 + h);
                go += __ldcg(p + 3072 + h);
            }
            float c = (e==0) ? creg0 : creg1;
            float ii = 1.f/(1.f+expf(-gi));
            float ff = 1.f/(1.f+expf(-gf));
            float oo = 1.f/(1.f+expf(-go));
            float gt = tanhf(gg);
            float cn = ff*c + ii*gt;
            float hn = oo*tanhf(cn);
            if (e==0) creg0 = cn; else creg1 = cn;
            __half hh = __float2half_rn(hn);
            g_h16[gid] = hh;
            g_Ah[(size_t)(t*64 + b)*KA + h] = hh;
        }
        gbar(target);
    }
}

// ============================================================
// Fallback per-step kernels (fp32 path; if residency check fails)
// ============================================================
__global__ __launch_bounds__(128)
void gates_gemm(const float* __restrict__ W_hh)
{
    __shared__ __align__(16) float As[64*20];
    __shared__ __align__(16) float Bs[16*132];
    const int n0 = blockIdx.x * 128;
    const int kbase = blockIdx.y * KCHUNK;
    const int tid = threadIdx.x;
    const int tx = tid & 15, ty = tid >> 4;

    ull acc[8][2][2];
    #pragma unroll
    for (int i=0;i<8;i++)
        #pragma unroll
        for (int q=0;q<2;q++){ acc[i][q][0]=0ull; acc[i][q][1]=0ull; }

    for (int kt = 0; kt < KCHUNK; kt += 16){
        const int kg0 = kbase + kt;
        #pragma unroll
        for (int l=0;l<2;l++){
            int f4 = tid + 128*l;
            int row = f4 >> 2, k4 = (f4 & 3) << 2;
            float4 v = *(const float4*)(g_h + row*1024 + kg0 + k4);
            *(float4*)(As + row*20 + k4) = v;
        }
        #pragma unroll
        for (int l=0;l<4;l++){
            int f4 = tid + 128*l;
            int row = f4 >> 2, k4 = (f4 & 3) << 2;
            float4 v = *(const float4*)(W_hh + (size_t)(n0+row)*1024 + kg0 + k4);
            Bs[(k4+0)*132 + row] = v.x;
            Bs[(k4+1)*132 + row] = v.y;
            Bs[(k4+2)*132 + row] = v.z;
            Bs[(k4+3)*132 + row] = v.w;
        }
        __syncthreads();
        #pragma unroll
        for (int kq=0;kq<4;kq++){
            float4 av[8];
            #pragma unroll
            for (int i=0;i<8;i++) av[i] = *(const float4*)(As + (ty*8+i)*20 + kq*4);
            #pragma unroll
            for (int kk=0;kk<4;kk++){
                ull a2[8];
                #pragma unroll
                for (int i=0;i<8;i++){
                    float a = (kk==0)?av[i].x:(kk==1)?av[i].y:(kk==2)?av[i].z:av[i].w;
                    a2[i] = dup2(a);
                }
                const int k = kq*4+kk;
                #pragma unroll
                for (int q=0;q<2;q++){
                    ulonglong2 bv = *(const ulonglong2*)(Bs + k*132 + tx*4 + q*64);
                    #pragma unroll
                    for (int i=0;i<8;i++){ ffma2(acc[i][q][0], a2[i], bv.x);
                                           ffma2(acc[i][q][1], a2[i], bv.y); }
                }
            }
        }
        __syncthreads();
    }
    float* outp = g_part + (size_t)blockIdx.y*(BB*G4H);
    #pragma unroll
    for (int i=0;i<8;i++){
        int m = ty*8 + i;
        #pragma unroll
        for (int q=0;q<2;q++){
            int n = n0 + tx*4 + q*64;
            float2 p0 = unpk(acc[i][q][0]);
            float2 p1 = unpk(acc[i][q][1]);
            *(float4*)(outp + (size_t)m*G4H + n) = make_float4(p0.x, p0.y, p1.x, p1.y);
        }
    }
}

__global__ void lstm_pw(int t)
{
    int gid = blockIdx.x*blockDim.x + threadIdx.x;
    int b = gid >> 10, h = gid & 1023;
    size_t prow = (size_t)(t*64 + b)*G4H;
    float gi = g_pre[prow + h];
    float gf = g_pre[prow + 1024 + h];
    float gg = g_pre[prow + 2048 + h];
    float go = g_pre[prow + 3072 + h];
    int base = b*G4H;
    #pragma unroll
    for (int s=0;s<KSPLIT;s++){
        const float* p = g_part + (size_t)s*(BB*G4H) + base;
        gi += p[h]; gf += p[1024+h]; gg += p[2048+h]; go += p[3072+h];
    }
    float c  = g_c[gid];
    float ii = 1.f/(1.f+expf(-gi));
    float ff = 1.f/(1.f+expf(-gf));
    float oo = 1.f/(1.f+expf(-go));
    float gt = tanhf(gg);
    float cn = ff*c + ii*gt;
    float hn = oo*tanhf(cn);
    g_c[gid] = cn; g_h[gid] = hn;
    g_Ah[(size_t)(t*64 + b)*KA + h] = __float2half_rn(hn);
}

// ============================================================
// Projection via mma.sync fp16 (R8 config)
// ============================================================
__global__ __launch_bounds__(256)
void proj_mma(float* __restrict__ out, const float* __restrict__ bias)
{
    extern __shared__ __align__(16) char sm[];
    const uint32_t uA = smem_u32(sm);
    const uint32_t uB = uA + NSTG*TSTA;
    const int tid = threadIdx.x;
    const int wid = tid >> 5, lane = tid & 31;
    const int m0 = blockIdx.x * 128;
    const int n0 = blockIdx.y * 256;
    const int wm = wid & 3, wn = wid >> 2;

    float acc[2][16][4];
    #pragma unroll
    for (int a=0;a<2;a++)
        #pragma unroll
        for (int j=0;j<16;j++)
            #pragma unroll
            for (int x=0;x<4;x++) acc[a][j][x] = 0.f;

    const __half* gA = g_Ah + (size_t)m0*KA;
    const __half* gB = g_Bh + (size_t)n0*KA;

    auto load_stage = [&](int slot, int ks){
        int k0 = ks * 32;
        uint32_t sA = uA + slot*TSTA;
        uint32_t sB = uB + slot*TSTB;
        #pragma unroll
        for (int i = 0; i < 2; i++){
            int idx = tid + 256*i;
            int row = idx >> 2, lc = idx & 3;
            cpasync16(sA + row*80 + lc*16, gA + (size_t)row*KA + k0 + lc*8);
        }
        #pragma unroll
        for (int i = 0; i < 4; i++){
            int idx = tid + 256*i;
            int row = idx >> 2, lc = idx & 3;
            cpasync16(sB + row*80 + lc*16, gB + (size_t)row*KA + k0 + lc*8);
        }
        cp_commit();
    };

    load_stage(0, 0);
    load_stage(1, 1);
    load_stage(2, 2);

    const int g  = lane >> 3;
    const int lr = lane & 7;

    for (int ks = 0; ks < NKS; ks++){
        asm volatile("cp.async.wait_group 2;");
        __syncthreads();
        int ld = ks + NSTG - 1;
        if (ld < NKS) load_stage(ld & (NSTG-1), ld);
        else cp_commit();

        const uint32_t bufA = uA + (ks & (NSTG-1))*TSTA;
        const uint32_t bufB = uB + (ks & (NSTG-1))*TSTB;

        #pragma unroll
        for (int kk = 0; kk < 32; kk += 16){
            uint32_t afr[2][4];
            #pragma unroll
            for (int mi = 0; mi < 2; mi++){
                int row = wm*32 + mi*16 + ((g & 1) ? 8 : 0) + lr;
                int kof = kk + (g >> 1)*8;
                ldm4(afr[mi], bufA + row*80 + kof*2);
            }
            uint32_t bfr[8][4];
            #pragma unroll
            for (int p = 0; p < 8; p++){
                int row = wn*128 + p*16 + (g >> 1)*8 + lr;
                int kof = kk + (g & 1)*8;
                ldm4(bfr[p], bufB + row*80 + kof*2);
            }
            #pragma unroll
            for (int mi = 0; mi < 2; mi++)
                #pragma unroll
                for (int j = 0; j < 16; j++){
                    int p = j >> 1, h2 = (j & 1)*2;
                    mma16816h(acc[mi][j], afr[mi], bfr[p][h2], bfr[p][h2+1]);
                }
        }
        __syncthreads();
    }

    const int tm = lane >> 2;
    const int tn = (lane & 3)*2;
    #pragma unroll
    for (int mi = 0; mi < 2; mi++){
        #pragma unroll
        for (int j = 0; j < 16; j++){
            int gn = n0 + wn*128 + j*8 + tn;
            float2 bb = *(const float2*)(bias + gn);
            int gm0 = m0 + wm*32 + mi*16 + tm;
            if (gm0 < MPROJ){
                float2 o; o.x = acc[mi][j][0] + bb.x; o.y = acc[mi][j][1] + bb.y;
                *(float2*)(out + (size_t)gm0*VTS + gn) = o;
            }
            int gm1 = gm0 + 8;
            if (gm1 < MPROJ){
                float2 o; o.x = acc[mi][j][2] + bb.x; o.y = acc[mi][j][3] + bb.y;
                *(float2*)(out + (size_t)gm1*VTS + gn) = o;
            }
        }
    }
}

extern "C" void kernel_launch(void* const* d_in, const int* in_sizes, int n_in,
                              void* d_out, int out_size)
{
    const int*   src      = (const int*)  d_in[0];
    const int*   pos      = (const int*)  d_in[2];
    const int*   tgt      = (const int*)  d_in[3];
    const float* enc_emb  = (const float*)d_in[4];
    const float* pos_emb  = (const float*)d_in[5];
    const float* cat_W    = (const float*)d_in[6];
    const float* cat_b    = (const float*)d_in[7];
    const float* scale_W  = (const float*)d_in[8];
    const float* scale_b  = (const float*)d_in[9];
    const float* dec_emb  = (const float*)d_in[10];
    const float* attn_W   = (const float*)d_in[11];
    const float* W_ih     = (const float*)d_in[13];
    const float* W_hh     = (const float*)d_in[14];
    const float* b_ih     = (const float*)d_in[15];
    const float* b_hh     = (const float*)d_in[16];
    const float* proj_W   = (const float*)d_in[17];
    const float* proj_b   = (const float*)d_in[18];
    float* out = (float*)d_out;

    cudaFuncSetAttribute(proj_mma, cudaFuncAttributeMaxDynamicSharedMemorySize, SM_PROJ);
    cudaFuncSetAttribute(pre_mma, cudaFuncAttributeMaxDynamicSharedMemorySize, SM_PROJ);
    cudaFuncSetAttribute(decoder_tc, cudaFuncAttributeMaxDynamicSharedMemorySize, DSM_TOT);

    int per_sm = 0, n_sm = 0;
    cudaOccupancyMaxActiveBlocksPerMultiprocessor(&per_sm, decoder_tc, 128, DSM_TOT);
    cudaDeviceGetAttribute(&n_sm, cudaDevAttrMultiProcessorCount, 0);
    const bool persistent_ok = ((long)per_sm * n_sm >= DCTA);

    // Weight conversions
    conv_w<<<32000, 256>>>(proj_W);
    conv_wih<<<4096, 256>>>(W_ih);
    conv_whh<<<4096, 256>>>(W_hh);

    // Encoder
    enc_gemm<<<dim3(25,4), 256>>>(src, pos, enc_emb, pos_emb, cat_W, cat_b);
    avg_kernel<<<64, 512>>>();
    h0_kernel<<<8192, 256>>>(scale_W, scale_b);

    // Loop-invariant attention context + fused fp16 pre-GEMM
    attn_kernel<<<64, 256>>>(attn_W, src);
    build_apre<<<3200, 256>>>(tgt, dec_emb);
    pre_mma<<<dim3(25,16), 256, SM_PROJ>>>(b_ih, b_hh);

    // Recurrence: persistent tensor-core decoder
    if (persistent_ok){
        decoder_tc<<<DCTA, 128, DSM_TOT>>>();
    } else {
        for (int t = 0; t < NSTEP; t++){
            gates_gemm<<<dim3(32, KSPLIT), 128>>>(W_hh);
            lstm_pw<<<256, 256>>>(t);
        }
    }

    // fp16 tensor-core projection
    proj_mma<<<dim3(25,125), 256, SM_PROJ>>>(out, proj_b);
}

// round 14
// speedup vs baseline: 1.7688x; 1.0450x over previous
#include <cuda_runtime.h>
#include <cuda_bf16.h>
#include <cuda_fp16.h>
#include <math.h>
#include <stdint.h>

#define BB 64
#define SS 50
#define EE 512
#define HH 1024
#define VTS 32000
#define NSTEP 49
#define MPROJ (NSTEP*BB)
#define MPAD  3200
#define G4H 4096
#define KSPLIT 8           /* fallback path split */
#define KCHUNK 128
#define KA 1024
#define DCTA 128           /* persistent decoder grid (single wave) */
#define DKS 4              /* persistent decoder k-splits */
#define DKC 256            /* K per decoder CTA */

typedef unsigned long long ull;

__device__ __forceinline__ ull dup2(float x){
    ull r; asm("mov.b64 %0, {%1, %1};" : "=l"(r) : "f"(x)); return r;
}
__device__ __forceinline__ void ffma2(ull &d, ull a, ull b){
    asm("fma.rn.f32x2 %0, %1, %2, %0;" : "+l"(d) : "l"(a), "l"(b));
}
__device__ __forceinline__ float2 unpk(ull v){
    float2 f; asm("mov.b64 {%0, %1}, %2;" : "=f"(f.x), "=f"(f.y) : "l"(v)); return f;
}
__device__ __forceinline__ uint32_t smem_u32(const void* p){
    uint32_t a;
    asm("{ .reg .u64 t; cvta.to.shared.u64 t, %1; cvt.u32.u64 %0, t; }" : "=r"(a) : "l"(p));
    return a;
}
__device__ __forceinline__ void cpasync16(uint32_t dst, const void* src){
    asm volatile("cp.async.cg.shared.global [%0], [%1], 16;" :: "r"(dst), "l"(src));
}
__device__ __forceinline__ void cp_commit(){
    asm volatile("cp.async.commit_group;");
}
__device__ __forceinline__ void ldm4(uint32_t* r, uint32_t a){
    asm volatile("ldmatrix.sync.aligned.m8n8.x4.shared.b16 {%0,%1,%2,%3}, [%4];"
        : "=r"(r[0]), "=r"(r[1]), "=r"(r[2]), "=r"(r[3]) : "r"(a));
}
__device__ __forceinline__ void mma16816h(float* c, const uint32_t* a, uint32_t b0, uint32_t b1){
    asm volatile("mma.sync.aligned.m16n8k16.row.col.f32.f16.f16.f32 "
        "{%0,%1,%2,%3}, {%4,%5,%6,%7}, {%8,%9}, {%0,%1,%2,%3};"
        : "+f"(c[0]), "+f"(c[1]), "+f"(c[2]), "+f"(c[3])
        : "r"(a[0]), "r"(a[1]), "r"(a[2]), "r"(a[3]), "r"(b0), "r"(b1));
}
__device__ __forceinline__ ull pack4h(float x, float y, float z, float w){
    __half h0 = __float2half_rn(x), h1 = __float2half_rn(y);
    __half h2 = __float2half_rn(z), h3 = __float2half_rn(w);
    ull p;
    asm("mov.b64 %0, {%1,%2,%3,%4};" : "=l"(p)
        : "h"(*(unsigned short*)&h0), "h"(*(unsigned short*)&h1),
          "h"(*(unsigned short*)&h2), "h"(*(unsigned short*)&h3));
    return p;
}

__device__ float g_enc_out[BB*SS*EE];
__device__ float g_avg[BB*EE];
__device__ float g_ctx[BB*EE];
__device__ float g_h[BB*HH];
__device__ float g_c[BB*HH];
__device__ float g_part[KSPLIT*BB*G4H];
__device__ float g_pre[MPAD*G4H];
__device__ __half g_h16[BB*HH];
__device__ __half g_Ah[(size_t)MPAD*KA];
__device__ __half g_Bh[(size_t)VTS*KA];
__device__ __half g_Apre[(size_t)MPAD*KA];    // reused: enc A first, then pre A
__device__ __half g_Wih16[(size_t)G4H*KA];
__device__ __half g_Whh16[(size_t)G4H*KA];
__device__ __half g_CatW16[(size_t)EE*KA];    // fp16 cat_W (512 x 1024)

__device__ unsigned g_bcount;
__device__ volatile unsigned g_bepoch;

__device__ __forceinline__ void gbar(unsigned &target){
    target += 1u;
    __syncthreads();
    if (threadIdx.x == 0){
        __threadfence();
        unsigned a = atomicAdd(&g_bcount, 1u);
        if (a == DCTA-1u){
            g_bcount = 0u;
            __threadfence();
            g_bepoch = g_bepoch + 1u;
        } else {
            while ((int)(g_bepoch - target) < 0) __nanosleep(64);
        }
    }
    __syncthreads();
}

// ============================================================
// Build fp16 A rows for the encoder GEMM: row r = [enc_emb[src[r]] | pos_emb[pos[r]]]
// ============================================================
__global__ __launch_bounds__(256)
void build_aenc(const int* __restrict__ src, const int* __restrict__ pos,
                const float* __restrict__ enc_emb, const float* __restrict__ pos_emb)
{
    int r = blockIdx.x;               // 0..3199 (= b*50+s)
    int c = threadIdx.x * 4;
    const float* srcp;
    if (c < 512) srcp = enc_emb + (size_t)src[r]*512 + c;
    else         srcp = pos_emb + (size_t)pos[r]*512 + (c - 512);
    float4 v = *(const float4*)srcp;
    *(ull*)(g_Apre + (size_t)r*KA + c) = pack4h(v.x, v.y, v.z, v.w);
}

__global__ __launch_bounds__(256)
void conv_catw(const float* __restrict__ W)
{
    size_t i = (size_t)blockIdx.x*blockDim.x + threadIdx.x;   // 131072 float4s
    float4 v = ((const float4*)W)[i];
    *(ull*)(g_CatW16 + i*4) = pack4h(v.x, v.y, v.z, v.w);
}

__global__ void avg_kernel()
{
    int b = blockIdx.x, e = threadIdx.x;
    float s = 0.f;
    #pragma unroll 5
    for (int si=0; si<SS; si++) s += g_enc_out[(b*SS+si)*EE + e];
    g_avg[b*EE + e] = s * (1.0f/50.0f);
}

__global__ __launch_bounds__(256)
void h0_kernel(const float* __restrict__ scale_W, const float* __restrict__ scale_b)
{
    int gw = blockIdx.x*8 + (threadIdx.x >> 5);
    int lane = threadIdx.x & 31;
    int b = gw >> 10, h = gw & 1023;
    const float* a = g_avg + b*EE;
    const float* w = scale_W + (size_t)h*EE;
    float s = 0.f;
    #pragma unroll
    for (int k = 0; k < 16; k++){
        int idx = k*32 + lane;
        s += a[idx] * w[idx];
    }
    #pragma unroll
    for (int o=16;o>0;o>>=1) s += __shfl_xor_sync(0xffffffffu, s, o);
    if (lane == 0){
        float v = fmaxf(s + scale_b[h], 0.f);
        g_h[b*HH + h] = v;
        g_c[b*HH + h] = v;
        g_h16[b*HH + h] = __float2half_rn(v);
    }
}

__global__ void attn_kernel(const float* __restrict__ attn_W, const int* __restrict__ src)
{
    int b = blockIdx.x, tid = threadIdx.x;
    __shared__ float sc[56];
    __shared__ float aw[56];
    int w = tid >> 5, lane = tid & 31;
    for (int s = w; s < SS; s += 8){
        const float* row = g_enc_out + (size_t)(b*SS+s)*EE;
        float a = 0.f;
        for (int e = lane; e < EE; e += 32) a += row[e]*attn_W[e];
        #pragma unroll
        for (int o=16;o>0;o>>=1) a += __shfl_xor_sync(0xffffffffu, a, o);
        if (lane==0) sc[s] = a;
    }
    __syncthreads();
    if (tid == 0){
        float mx = -1e30f;
        for (int s=0;s<SS;s++) mx = fmaxf(mx, sc[s]);
        float tot = 0.f;
        for (int s=0;s<SS;s++){
            float e = (src[b*SS+s]==0) ? 0.f : expf(sc[s]-mx);
            aw[s] = e; tot += e;
        }
        float inv = 1.f/tot;
        for (int s=0;s<SS;s++) aw[s] *= inv;
    }
    __syncthreads();
    for (int e = tid; e < EE; e += blockDim.x){
        float a = 0.f;
        #pragma unroll 5
        for (int s=0;s<SS;s++) a += aw[s]*g_enc_out[(size_t)(b*SS+s)*EE + e];
        g_ctx[b*EE + e] = a;
    }
}

__global__ __launch_bounds__(256)
void build_apre(const int* __restrict__ tgt, const float* __restrict__ dec_emb)
{
    int r = blockIdx.x;
    int b = r & 63, t = r >> 6;
    int c = threadIdx.x * 4;
    const float* srcp;
    if (c < 512){
        int tok = tgt[b*50 + t];
        srcp = dec_emb + (size_t)tok*512 + c;
    } else {
        srcp = g_ctx + b*EE + (c - 512);
    }
    float4 v = *(const float4*)srcp;
    *(ull*)(g_Apre + (size_t)r*KA + c) = pack4h(v.x, v.y, v.z, v.w);
}

__global__ __launch_bounds__(256)
void conv_wih(const float* __restrict__ W)
{
    size_t i = (size_t)blockIdx.x*blockDim.x + threadIdx.x;
    float4 v = ((const float4*)W)[i];
    *(ull*)(g_Wih16 + i*4) = pack4h(v.x, v.y, v.z, v.w);
}
__global__ __launch_bounds__(256)
void conv_whh(const float* __restrict__ W)
{
    size_t i = (size_t)blockIdx.x*blockDim.x + threadIdx.x;
    float4 v = ((const float4*)W)[i];
    *(ull*)(g_Whh16 + i*4) = pack4h(v.x, v.y, v.z, v.w);
}
__global__ __launch_bounds__(256)
void conv_w(const float* __restrict__ W)
{
    size_t i = (size_t)blockIdx.x*blockDim.x + threadIdx.x;
    float4 v = ((const float4*)W)[i];
    *(ull*)(g_Bh + i*4) = pack4h(v.x, v.y, v.z, v.w);
}

#define NSTG 4
#define TSTA 10240
#define TSTB 20480
#define SM_PROJ (NSTG*(TSTA+TSTB))
#define NKS (KA/32)

// ============================================================
// Generic fp16 GEMM body (128m x 256n CTA tile, K=1024) as macro-like inline:
// instantiated for enc (N=512 out, +cat_b), pre (out g_pre, +b_ih+b_hh), proj.
// ============================================================

// ---- encoder GEMM: out = A_enc . CatW^T + cat_b -> g_enc_out (rows 512 wide)
__global__ __launch_bounds__(256)
void enc_mma(const float* __restrict__ bias)
{
    extern __shared__ __align__(16) char sm[];
    const uint32_t uA = smem_u32(sm);
    const uint32_t uB = uA + NSTG*TSTA;
    const int tid = threadIdx.x;
    const int wid = tid >> 5, lane = tid & 31;
    const int m0 = blockIdx.x * 128;
    const int n0 = blockIdx.y * 256;
    const int wm = wid & 3, wn = wid >> 2;

    float acc[2][16][4];
    #pragma unroll
    for (int a=0;a<2;a++)
        #pragma unroll
        for (int j=0;j<16;j++)
            #pragma unroll
            for (int x=0;x<4;x++) acc[a][j][x] = 0.f;

    const __half* gA = g_Apre + (size_t)m0*KA;
    const __half* gB = g_CatW16 + (size_t)n0*KA;

    auto load_stage = [&](int slot, int ks){
        int k0 = ks * 32;
        uint32_t sA = uA + slot*TSTA;
        uint32_t sB = uB + slot*TSTB;
        #pragma unroll
        for (int i = 0; i < 2; i++){
            int idx = tid + 256*i;
            int row = idx >> 2, lc = idx & 3;
            cpasync16(sA + row*80 + lc*16, gA + (size_t)row*KA + k0 + lc*8);
        }
        #pragma unroll
        for (int i = 0; i < 4; i++){
            int idx = tid + 256*i;
            int row = idx >> 2, lc = idx & 3;
            cpasync16(sB + row*80 + lc*16, gB + (size_t)row*KA + k0 + lc*8);
        }
        cp_commit();
    };

    load_stage(0, 0); load_stage(1, 1); load_stage(2, 2);

    const int g  = lane >> 3;
    const int lr = lane & 7;

    for (int ks = 0; ks < NKS; ks++){
        asm volatile("cp.async.wait_group 2;");
        __syncthreads();
        int ld = ks + NSTG - 1;
        if (ld < NKS) load_stage(ld & (NSTG-1), ld);
        else cp_commit();

        const uint32_t bufA = uA + (ks & (NSTG-1))*TSTA;
        const uint32_t bufB = uB + (ks & (NSTG-1))*TSTB;

        #pragma unroll
        for (int kk = 0; kk < 32; kk += 16){
            uint32_t afr[2][4];
            #pragma unroll
            for (int mi = 0; mi < 2; mi++){
                int row = wm*32 + mi*16 + ((g & 1) ? 8 : 0) + lr;
                int kof = kk + (g >> 1)*8;
                ldm4(afr[mi], bufA + row*80 + kof*2);
            }
            uint32_t bfr[8][4];
            #pragma unroll
            for (int p = 0; p < 8; p++){
                int row = wn*128 + p*16 + (g >> 1)*8 + lr;
                int kof = kk + (g & 1)*8;
                ldm4(bfr[p], bufB + row*80 + kof*2);
            }
            #pragma unroll
            for (int mi = 0; mi < 2; mi++)
                #pragma unroll
                for (int j = 0; j < 16; j++){
                    int p = j >> 1, h2 = (j & 1)*2;
                    mma16816h(acc[mi][j], afr[mi], bfr[p][h2], bfr[p][h2+1]);
                }
        }
        __syncthreads();
    }

    const int tm = lane >> 2;
    const int tn = (lane & 3)*2;
    #pragma unroll
    for (int mi = 0; mi < 2; mi++){
        #pragma unroll
        for (int j = 0; j < 16; j++){
            int gn = n0 + wn*128 + j*8 + tn;
            float2 bb = *(const float2*)(bias + gn);
            int gm0 = m0 + wm*32 + mi*16 + tm;
            {
                float2 o; o.x = acc[mi][j][0] + bb.x; o.y = acc[mi][j][1] + bb.y;
                *(float2*)(g_enc_out + (size_t)gm0*EE + gn) = o;
            }
            int gm1 = gm0 + 8;
            {
                float2 o; o.x = acc[mi][j][2] + bb.x; o.y = acc[mi][j][3] + bb.y;
                *(float2*)(g_enc_out + (size_t)gm1*EE + gn) = o;
            }
        }
    }
}

// ---- pre-GEMM: g_pre = A_pre . W_ih^T + b_ih + b_hh
__global__ __launch_bounds__(256)
void pre_mma(const float* __restrict__ b_ih, const float* __restrict__ b_hh)
{
    extern __shared__ __align__(16) char sm[];
    const uint32_t uA = smem_u32(sm);
    const uint32_t uB = uA + NSTG*TSTA;
    const int tid = threadIdx.x;
    const int wid = tid >> 5, lane = tid & 31;
    const int m0 = blockIdx.x * 128;
    const int n0 = blockIdx.y * 256;
    const int wm = wid & 3, wn = wid >> 2;

    float acc[2][16][4];
    #pragma unroll
    for (int a=0;a<2;a++)
        #pragma unroll
        for (int j=0;j<16;j++)
            #pragma unroll
            for (int x=0;x<4;x++) acc[a][j][x] = 0.f;

    const __half* gA = g_Apre + (size_t)m0*KA;
    const __half* gB = g_Wih16 + (size_t)n0*KA;

    auto load_stage = [&](int slot, int ks){
        int k0 = ks * 32;
        uint32_t sA = uA + slot*TSTA;
        uint32_t sB = uB + slot*TSTB;
        #pragma unroll
        for (int i = 0; i < 2; i++){
            int idx = tid + 256*i;
            int row = idx >> 2, lc = idx & 3;
            cpasync16(sA + row*80 + lc*16, gA + (size_t)row*KA + k0 + lc*8);
        }
        #pragma unroll
        for (int i = 0; i < 4; i++){
            int idx = tid + 256*i;
            int row = idx >> 2, lc = idx & 3;
            cpasync16(sB + row*80 + lc*16, gB + (size_t)row*KA + k0 + lc*8);
        }
        cp_commit();
    };

    load_stage(0, 0); load_stage(1, 1); load_stage(2, 2);

    const int g  = lane >> 3;
    const int lr = lane & 7;

    for (int ks = 0; ks < NKS; ks++){
        asm volatile("cp.async.wait_group 2;");
        __syncthreads();
        int ld = ks + NSTG - 1;
        if (ld < NKS) load_stage(ld & (NSTG-1), ld);
        else cp_commit();

        const uint32_t bufA = uA + (ks & (NSTG-1))*TSTA;
        const uint32_t bufB = uB + (ks & (NSTG-1))*TSTB;

        #pragma unroll
        for (int kk = 0; kk < 32; kk += 16){
            uint32_t afr[2][4];
            #pragma unroll
            for (int mi = 0; mi < 2; mi++){
                int row = wm*32 + mi*16 + ((g & 1) ? 8 : 0) + lr;
                int kof = kk + (g >> 1)*8;
                ldm4(afr[mi], bufA + row*80 + kof*2);
            }
            uint32_t bfr[8][4];
            #pragma unroll
            for (int p = 0; p < 8; p++){
                int row = wn*128 + p*16 + (g >> 1)*8 + lr;
                int kof = kk + (g & 1)*8;
                ldm4(bfr[p], bufB + row*80 + kof*2);
            }
            #pragma unroll
            for (int mi = 0; mi < 2; mi++)
                #pragma unroll
                for (int j = 0; j < 16; j++){
                    int p = j >> 1, h2 = (j & 1)*2;
                    mma16816h(acc[mi][j], afr[mi], bfr[p][h2], bfr[p][h2+1]);
                }
        }
        __syncthreads();
    }

    const int tm = lane >> 2;
    const int tn = (lane & 3)*2;
    #pragma unroll
    for (int mi = 0; mi < 2; mi++){
        #pragma unroll
        for (int j = 0; j < 16; j++){
            int gn = n0 + wn*128 + j*8 + tn;
            float2 bi = *(const float2*)(b_ih + gn);
            float2 bh = *(const float2*)(b_hh + gn);
            float bx = bi.x + bh.x, by = bi.y + bh.y;
            int gm0 = m0 + wm*32 + mi*16 + tm;
            {
                float2 o; o.x = acc[mi][j][0] + bx; o.y = acc[mi][j][1] + by;
                *(float2*)(g_pre + (size_t)gm0*G4H + gn) = o;
            }
            int gm1 = gm0 + 8;
            {
                float2 o; o.x = acc[mi][j][2] + bx; o.y = acc[mi][j][3] + by;
                *(float2*)(g_pre + (size_t)gm1*G4H + gn) = o;
            }
        }
    }
}

// ============================================================
// PERSISTENT tensor-core decoder, split-K=4, single wave (128 CTAs).
// CTA (ntile 0..31, ks 0..3); K=256 per CTA.
// SMEM pitch 528B (256 fp16 + 8 pad) -> conflict-free ldmatrix.
// LSTM: 4 cells per thread.
// ============================================================
#define DPITCH 528
#define DSM_AS 0                            /* 64 * 528 = 33792 */
#define DSM_BS (64*DPITCH)
#define DSM_TOT (DSM_BS + 128*DPITCH)       /* 33792 + 67584 = 101376 */

__global__ __launch_bounds__(128)
void decoder_tc(void)
{
    extern __shared__ __align__(16) char dsm[];
    const uint32_t uAs = smem_u32(dsm) + DSM_AS;
    const uint32_t uBs = smem_u32(dsm) + DSM_BS;
    const int cid = blockIdx.x;
    const int ntile = cid & 31;
    const int ksplit = cid >> 5;            // 0..3
    const int n0 = ntile * 128;
    const int kbase = ksplit * DKC;
    const int tid = threadIdx.x;
    const int wid = tid >> 5, lane = tid & 31;
    unsigned target = g_bepoch;

    // one-time: W_hh fp16 slice 128n x 256k -> SMEM
    #pragma unroll
    for (int l = 0; l < 32; l++){
        int idx = tid + 128*l;              // 4096 16B chunks
        int n = idx >> 5, kc = (idx & 31)*8;
        uint4 v = *(const uint4*)(g_Whh16 + (size_t)(n0+n)*KA + kbase + kc);
        *(uint4*)(dsm + DSM_BS + n*DPITCH + kc*2) = v;
    }

    // LSTM cell ownership: 4 cells per thread
    const int gidb = cid*128 + tid;
    float creg[4];
    #pragma unroll
    for (int e = 0; e < 4; e++) creg[e] = g_c[gidb + e*16384];

    const int g  = lane >> 3;
    const int lr = lane & 7;
    const int tm = lane >> 2;
    const int tn = (lane & 3)*2;

    for (int t = 0; t < NSTEP; t++){
        // ---- stage h fp16 slice 64m x 256k
        #pragma unroll
        for (int l = 0; l < 16; l++){
            int idx = tid + 128*l;          // 2048 16B chunks
            int m = idx >> 5, kc = (idx & 31)*8;
            uint4 v = __ldcg((const uint4*)(g_h16 + m*HH + kbase + kc));
            *(uint4*)(dsm + DSM_AS + m*DPITCH + kc*2) = v;
        }
        __syncthreads();

        // ---- GEMM M64 x N128 x K256 (warp: M16 x N128)
        float acc[16][4];
        #pragma unroll
        for (int j=0;j<16;j++)
            #pragma unroll
            for (int x=0;x<4;x++) acc[j][x] = 0.f;

        #pragma unroll
        for (int kk = 0; kk < DKC; kk += 16){
            uint32_t afr[4];
            {
                int row = wid*16 + ((g & 1) ? 8 : 0) + lr;
                int kof = kk + (g >> 1)*8;
                ldm4(afr, uAs + row*DPITCH + kof*2);
            }
            uint32_t bfr[8][4];
            #pragma unroll
            for (int p = 0; p < 8; p++){
                int row = p*16 + (g >> 1)*8 + lr;
                int kof = kk + (g & 1)*8;
                ldm4(bfr[p], uBs + row*DPITCH + kof*2);
            }
            #pragma unroll
            for (int j = 0; j < 16; j++){
                int p = j >> 1, h2 = (j & 1)*2;
                mma16816h(acc[j], afr, bfr[p][h2], bfr[p][h2+1]);
            }
        }

        // ---- store partials
        {
            float* outp = g_part + (size_t)ksplit*(BB*G4H);
            #pragma unroll
            for (int j = 0; j < 16; j++){
                int n = n0 + j*8 + tn;
                int m0r = wid*16 + tm;
                *(float2*)(outp + (size_t)m0r*G4H + n) =
                    make_float2(acc[j][0], acc[j][1]);
                *(float2*)(outp + (size_t)(m0r+8)*G4H + n) =
                    make_float2(acc[j][2], acc[j][3]);
            }
        }
        __syncthreads();
        gbar(target);

        // ---- LSTM pointwise: 4 cells per thread
        #pragma unroll
        for (int e = 0; e < 4; e++){
            int gid = gidb + e*16384;
            int b = gid >> 10, h = gid & 1023;
            size_t prow = (size_t)(t*64 + b)*G4H;
            float gi = g_pre[prow + h];
            float gf = g_pre[prow + 1024 + h];
            float gg = g_pre[prow + 2048 + h];
            float go = g_pre[prow + 3072 + h];
            int base = b*G4H;
            #pragma unroll
            for (int s=0;s<DKS;s++){
                const float* p = g_part + (size_t)s*(BB*G4H) + base;
                gi += __ldcg(p + h);
                gf += __ldcg(p + 1024 + h);
                gg += __ldcg(p + 2048 + h);
                go += __ldcg(p + 3072 + h);
            }
            float c = creg[e];
            float ii = 1.f/(1.f+expf(-gi));
            float ff = 1.f/(1.f+expf(-gf));
            float oo = 1.f/(1.f+expf(-go));
            float gt = tanhf(gg);
            float cn = ff*c + ii*gt;
            float hn = oo*tanhf(cn);
            creg[e] = cn;
            __half hh = __float2half_rn(hn);
            g_h16[gid] = hh;
            g_Ah[(size_t)(t*64 + b)*KA + h] = hh;
        }
        gbar(target);
    }
}

// ============================================================
// Fallback per-step kernels (fp32 path)
// ============================================================
__global__ __launch_bounds__(128)
void gates_gemm(const float* __restrict__ W_hh)
{
    __shared__ __align__(16) float As[64*20];
    __shared__ __align__(16) float Bs[16*132];
    const int n0 = blockIdx.x * 128;
    const int kbase = blockIdx.y * KCHUNK;
    const int tid = threadIdx.x;
    const int tx = tid & 15, ty = tid >> 4;

    ull acc[8][2][2];
    #pragma unroll
    for (int i=0;i<8;i++)
        #pragma unroll
        for (int q=0;q<2;q++){ acc[i][q][0]=0ull; acc[i][q][1]=0ull; }

    for (int kt = 0; kt < KCHUNK; kt += 16){
        const int kg0 = kbase + kt;
        #pragma unroll
        for (int l=0;l<2;l++){
            int f4 = tid + 128*l;
            int row = f4 >> 2, k4 = (f4 & 3) << 2;
            float4 v = *(const float4*)(g_h + row*1024 + kg0 + k4);
            *(float4*)(As + row*20 + k4) = v;
        }
        #pragma unroll
        for (int l=0;l<4;l++){
            int f4 = tid + 128*l;
            int row = f4 >> 2, k4 = (f4 & 3) << 2;
            float4 v = *(const float4*)(W_hh + (size_t)(n0+row)*1024 + kg0 + k4);
            Bs[(k4+0)*132 + row] = v.x;
            Bs[(k4+1)*132 + row] = v.y;
            Bs[(k4+2)*132 + row] = v.z;
            Bs[(k4+3)*132 + row] = v.w;
        }
        __syncthreads();
        #pragma unroll
        for (int kq=0;kq<4;kq++){
            float4 av[8];
            #pragma unroll
            for (int i=0;i<8;i++) av[i] = *(const float4*)(As + (ty*8+i)*20 + kq*4);
            #pragma unroll
            for (int kk=0;kk<4;kk++){
                ull a2[8];
                #pragma unroll
                for (int i=0;i<8;i++){
                    float a = (kk==0)?av[i].x:(kk==1)?av[i].y:(kk==2)?av[i].z:av[i].w;
                    a2[i] = dup2(a);
                }
                const int k = kq*4+kk;
                #pragma unroll
                for (int q=0;q<2;q++){
                    ulonglong2 bv = *(const ulonglong2*)(Bs + k*132 + tx*4 + q*64);
                    #pragma unroll
                    for (int i=0;i<8;i++){ ffma2(acc[i][q][0], a2[i], bv.x);
                                           ffma2(acc[i][q][1], a2[i], bv.y); }
                }
            }
        }
        __syncthreads();
    }
    float* outp = g_part + (size_t)blockIdx.y*(BB*G4H);
    #pragma unroll
    for (int i=0;i<8;i++){
        int m = ty*8 + i;
        #pragma unroll
        for (int q=0;q<2;q++){
            int n = n0 + tx*4 + q*64;
            float2 p0 = unpk(acc[i][q][0]);
            float2 p1 = unpk(acc[i][q][1]);
            *(float4*)(outp + (size_t)m*G4H + n) = make_float4(p0.x, p0.y, p1.x, p1.y);
        }
    }
}

__global__ void lstm_pw(int t)
{
    int gid = blockIdx.x*blockDim.x + threadIdx.x;
    int b = gid >> 10, h = gid & 1023;
    size_t prow = (size_t)(t*64 + b)*G4H;
    float gi = g_pre[prow + h];
    float gf = g_pre[prow + 1024 + h];
    float gg = g_pre[prow + 2048 + h];
    float go = g_pre[prow + 3072 + h];
    int base = b*G4H;
    #pragma unroll
    for (int s=0;s<KSPLIT;s++){
        const float* p = g_part + (size_t)s*(BB*G4H) + base;
        gi += p[h]; gf += p[1024+h]; gg += p[2048+h]; go += p[3072+h];
    }
    float c  = g_c[gid];
    float ii = 1.f/(1.f+expf(-gi));
    float ff = 1.f/(1.f+expf(-gf));
    float oo = 1.f/(1.f+expf(-go));
    float gt = tanhf(gg);
    float cn = ff*c + ii*gt;
    float hn = oo*tanhf(cn);
    g_c[gid] = cn; g_h[gid] = hn;
    g_Ah[(size_t)(t*64 + b)*KA + h] = __float2half_rn(hn);
}

// ============================================================
// Projection via mma.sync fp16
// ============================================================
__global__ __launch_bounds__(256)
void proj_mma(float* __restrict__ out, const float* __restrict__ bias)
{
    extern __shared__ __align__(16) char sm[];
    const uint32_t uA = smem_u32(sm);
    const uint32_t uB = uA + NSTG*TSTA;
    const int tid = threadIdx.x;
    const int wid = tid >> 5, lane = tid & 31;
    const int m0 = blockIdx.x * 128;
    const int n0 = blockIdx.y * 256;
    const int wm = wid & 3, wn = wid >> 2;

    float acc[2][16][4];
    #pragma unroll
    for (int a=0;a<2;a++)
        #pragma unroll
        for (int j=0;j<16;j++)
            #pragma unroll
            for (int x=0;x<4;x++) acc[a][j][x] = 0.f;

    const __half* gA = g_Ah + (size_t)m0*KA;
    const __half* gB = g_Bh + (size_t)n0*KA;

    auto load_stage = [&](int slot, int ks){
        int k0 = ks * 32;
        uint32_t sA = uA + slot*TSTA;
        uint32_t sB = uB + slot*TSTB;
        #pragma unroll
        for (int i = 0; i < 2; i++){
            int idx = tid + 256*i;
            int row = idx >> 2, lc = idx & 3;
            cpasync16(sA + row*80 + lc*16, gA + (size_t)row*KA + k0 + lc*8);
        }
        #pragma unroll
        for (int i = 0; i < 4; i++){
            int idx = tid + 256*i;
            int row = idx >> 2, lc = idx & 3;
            cpasync16(sB + row*80 + lc*16, gB + (size_t)row*KA + k0 + lc*8);
        }
        cp_commit();
    };

    load_stage(0, 0); load_stage(1, 1); load_stage(2, 2);

    const int g  = lane >> 3;
    const int lr = lane & 7;

    for (int ks = 0; ks < NKS; ks++){
        asm volatile("cp.async.wait_group 2;");
        __syncthreads();
        int ld = ks + NSTG - 1;
        if (ld < NKS) load_stage(ld & (NSTG-1), ld);
        else cp_commit();

        const uint32_t bufA = uA + (ks & (NSTG-1))*TSTA;
        const uint32_t bufB = uB + (ks & (NSTG-1))*TSTB;

        #pragma unroll
        for (int kk = 0; kk < 32; kk += 16){
            uint32_t afr[2][4];
            #pragma unroll
            for (int mi = 0; mi < 2; mi++){
                int row = wm*32 + mi*16 + ((g & 1) ? 8 : 0) + lr;
                int kof = kk + (g >> 1)*8;
                ldm4(afr[mi], bufA + row*80 + kof*2);
            }
            uint32_t bfr[8][4];
            #pragma unroll
            for (int p = 0; p < 8; p++){
                int row = wn*128 + p*16 + (g >> 1)*8 + lr;
                int kof = kk + (g & 1)*8;
                ldm4(bfr[p], bufB + row*80 + kof*2);
            }
            #pragma unroll
            for (int mi = 0; mi < 2; mi++)
                #pragma unroll
                for (int j = 0; j < 16; j++){
                    int p = j >> 1, h2 = (j & 1)*2;
                    mma16816h(acc[mi][j], afr[mi], bfr[p][h2], bfr[p][h2+1]);
                }
        }
        __syncthreads();
    }

    const int tm = lane >> 2;
    const int tn = (lane & 3)*2;
    #pragma unroll
    for (int mi = 0; mi < 2; mi++){
        #pragma unroll
        for (int j = 0; j < 16; j++){
            int gn = n0 + wn*128 + j*8 + tn;
            float2 bb = *(const float2*)(bias + gn);
            int gm0 = m0 + wm*32 + mi*16 + tm;
            if (gm0 < MPROJ){
                float2 o; o.x = acc[mi][j][0] + bb.x; o.y = acc[mi][j][1] + bb.y;
                *(float2*)(out + (size_t)gm0*VTS + gn) = o;
            }
            int gm1 = gm0 + 8;
            if (gm1 < MPROJ){
                float2 o; o.x = acc[mi][j][2] + bb.x; o.y = acc[mi][j][3] + bb.y;
                *(float2*)(out + (size_t)gm1*VTS + gn) = o;
            }
        }
    }
}

extern "C" void kernel_launch(void* const* d_in, const int* in_sizes, int n_in,
                              void* d_out, int out_size)
{
    const int*   src      = (const int*)  d_in[0];
    const int*   pos      = (const int*)  d_in[2];
    const int*   tgt      = (const int*)  d_in[3];
    const float* enc_emb  = (const float*)d_in[4];
    const float* pos_emb  = (const float*)d_in[5];
    const float* cat_W    = (const float*)d_in[6];
    const float* cat_b    = (const float*)d_in[7];
    const float* scale_W  = (const float*)d_in[8];
    const float* scale_b  = (const float*)d_in[9];
    const float* dec_emb  = (const float*)d_in[10];
    const float* attn_W   = (const float*)d_in[11];
    const float* W_ih     = (const float*)d_in[13];
    const float* W_hh     = (const float*)d_in[14];
    const float* b_ih     = (const float*)d_in[15];
    const float* b_hh     = (const float*)d_in[16];
    const float* proj_W   = (const float*)d_in[17];
    const float* proj_b   = (const float*)d_in[18];
    float* out = (float*)d_out;

    cudaFuncSetAttribute(proj_mma, cudaFuncAttributeMaxDynamicSharedMemorySize, SM_PROJ);
    cudaFuncSetAttribute(pre_mma, cudaFuncAttributeMaxDynamicSharedMemorySize, SM_PROJ);
    cudaFuncSetAttribute(enc_mma, cudaFuncAttributeMaxDynamicSharedMemorySize, SM_PROJ);
    cudaFuncSetAttribute(decoder_tc, cudaFuncAttributeMaxDynamicSharedMemorySize, DSM_TOT);

    int per_sm = 0, n_sm = 0;
    cudaOccupancyMaxActiveBlocksPerMultiprocessor(&per_sm, decoder_tc, 128, DSM_TOT);
    cudaDeviceGetAttribute(&n_sm, cudaDevAttrMultiProcessorCount, 0);
    const bool persistent_ok = ((long)per_sm * n_sm >= DCTA);

    // Weight conversions
    conv_w<<<32000, 256>>>(proj_W);
    conv_catw<<<512, 256>>>(cat_W);
    conv_wih<<<4096, 256>>>(W_ih);
    conv_whh<<<4096, 256>>>(W_hh);

    // Encoder (fp16 tensor cores)
    build_aenc<<<3200, 256>>>(src, pos, enc_emb, pos_emb);
    enc_mma<<<dim3(25,2), 256, SM_PROJ>>>(cat_b);
    avg_kernel<<<64, 512>>>();
    h0_kernel<<<8192, 256>>>(scale_W, scale_b);

    // Loop-invariant attention context + fused fp16 pre-GEMM
    attn_kernel<<<64, 256>>>(attn_W, src);
    build_apre<<<3200, 256>>>(tgt, dec_emb);
    pre_mma<<<dim3(25,16), 256, SM_PROJ>>>(b_ih, b_hh);

    // Recurrence: persistent tensor-core decoder (split-K=4, single wave)
    if (persistent_ok){
        decoder_tc<<<DCTA, 128, DSM_TOT>>>();
    } else {
        for (int t = 0; t < NSTEP; t++){
            gates_gemm<<<dim3(32, KSPLIT), 128>>>(W_hh);
            lstm_pw<<<256, 256>>>(t);
        }
    }

    // fp16 tensor-core projection
    proj_mma<<<dim3(25,125), 256, SM_PROJ>>>(out, proj_b);
}

// round 15
// speedup vs baseline: 1.8104x; 1.0235x over previous
#include <cuda_runtime.h>
#include <cuda_bf16.h>
#include <cuda_fp16.h>
#include <math.h>
#include <stdint.h>

#define BB 64
#define SS 50
#define EE 512
#define HH 1024
#define VTS 32000
#define NSTEP 49
#define MPROJ (NSTEP*BB)
#define MPAD  3200
#define G4H 4096
#define KSPLIT 8           /* fallback path split */
#define KCHUNK 128
#define KA 1024
#define DCTA 128           /* persistent decoder grid (single wave) */
#define DKS 4              /* persistent decoder k-splits */
#define DKC 256            /* K per decoder CTA */

typedef unsigned long long ull;

__device__ __forceinline__ ull dup2(float x){
    ull r; asm("mov.b64 %0, {%1, %1};" : "=l"(r) : "f"(x)); return r;
}
__device__ __forceinline__ void ffma2(ull &d, ull a, ull b){
    asm("fma.rn.f32x2 %0, %1, %2, %0;" : "+l"(d) : "l"(a), "l"(b));
}
__device__ __forceinline__ float2 unpk(ull v){
    float2 f; asm("mov.b64 {%0, %1}, %2;" : "=f"(f.x), "=f"(f.y) : "l"(v)); return f;
}
__device__ __forceinline__ uint32_t smem_u32(const void* p){
    uint32_t a;
    asm("{ .reg .u64 t; cvta.to.shared.u64 t, %1; cvt.u32.u64 %0, t; }" : "=r"(a) : "l"(p));
    return a;
}
__device__ __forceinline__ void cpasync16(uint32_t dst, const void* src){
    asm volatile("cp.async.cg.shared.global [%0], [%1], 16;" :: "r"(dst), "l"(src));
}
__device__ __forceinline__ void cp_commit(){
    asm volatile("cp.async.commit_group;");
}
__device__ __forceinline__ void ldm4(uint32_t* r, uint32_t a){
    asm volatile("ldmatrix.sync.aligned.m8n8.x4.shared.b16 {%0,%1,%2,%3}, [%4];"
        : "=r"(r[0]), "=r"(r[1]), "=r"(r[2]), "=r"(r[3]) : "r"(a));
}
__device__ __forceinline__ void mma16816h(float* c, const uint32_t* a, uint32_t b0, uint32_t b1){
    asm volatile("mma.sync.aligned.m16n8k16.row.col.f32.f16.f16.f32 "
        "{%0,%1,%2,%3}, {%4,%5,%6,%7}, {%8,%9}, {%0,%1,%2,%3};"
        : "+f"(c[0]), "+f"(c[1]), "+f"(c[2]), "+f"(c[3])
        : "r"(a[0]), "r"(a[1]), "r"(a[2]), "r"(a[3]), "r"(b0), "r"(b1));
}
__device__ __forceinline__ ull pack4h(float x, float y, float z, float w){
    __half h0 = __float2half_rn(x), h1 = __float2half_rn(y);
    __half h2 = __float2half_rn(z), h3 = __float2half_rn(w);
    ull p;
    asm("mov.b64 %0, {%1,%2,%3,%4};" : "=l"(p)
        : "h"(*(unsigned short*)&h0), "h"(*(unsigned short*)&h1),
          "h"(*(unsigned short*)&h2), "h"(*(unsigned short*)&h3));
    return p;
}

__device__ float g_enc_out[BB*SS*EE];
__device__ float g_avg[BB*EE];
__device__ float g_ctx[BB*EE];
__device__ float g_h[BB*HH];
__device__ float g_c[BB*HH];
__device__ float g_part[KSPLIT*BB*G4H];
__device__ float g_pre[MPAD*G4H];
__device__ __half g_h16[BB*HH];
__device__ __half g_Ah[(size_t)MPAD*KA];
__device__ __half g_Bh[(size_t)VTS*KA];
__device__ __half g_Apre[(size_t)MPAD*KA];    // reused: enc A first, then pre A
__device__ __half g_Wih16[(size_t)G4H*KA];
__device__ __half g_Whh16[(size_t)G4H*KA];
__device__ __half g_CatW16[(size_t)EE*KA];

__device__ unsigned g_bcount;
__device__ volatile unsigned g_bepoch;

__device__ __forceinline__ void gbar(unsigned &target){
    target += 1u;
    __syncthreads();
    if (threadIdx.x == 0){
        __threadfence();
        unsigned a = atomicAdd(&g_bcount, 1u);
        if (a == DCTA-1u){
            g_bcount = 0u;
            __threadfence();
            g_bepoch = g_bepoch + 1u;
        } else {
            while ((int)(g_bepoch - target) < 0) __nanosleep(64);
        }
    }
    __syncthreads();
}

// ============================================================
// fp16 A rows for encoder GEMM: row r = [enc_emb[src[r]] | pos_emb[pos[r]]]
// ============================================================
__global__ __launch_bounds__(256)
void build_aenc(const int* __restrict__ src, const int* __restrict__ pos,
                const float* __restrict__ enc_emb, const float* __restrict__ pos_emb)
{
    int r = blockIdx.x;
    int c = threadIdx.x * 4;
    const float* srcp;
    if (c < 512) srcp = enc_emb + (size_t)src[r]*512 + c;
    else         srcp = pos_emb + (size_t)pos[r]*512 + (c - 512);
    float4 v = *(const float4*)srcp;
    *(ull*)(g_Apre + (size_t)r*KA + c) = pack4h(v.x, v.y, v.z, v.w);
}

__global__ __launch_bounds__(256)
void conv_catw(const float* __restrict__ W)
{
    size_t i = (size_t)blockIdx.x*blockDim.x + threadIdx.x;
    float4 v = ((const float4*)W)[i];
    *(ull*)(g_CatW16 + i*4) = pack4h(v.x, v.y, v.z, v.w);
}

__global__ void avg_kernel()
{
    int b = blockIdx.x, e = threadIdx.x;
    float s = 0.f;
    #pragma unroll 5
    for (int si=0; si<SS; si++) s += g_enc_out[(b*SS+si)*EE + e];
    g_avg[b*EE + e] = s * (1.0f/50.0f);
}

__global__ __launch_bounds__(256)
void h0_kernel(const float* __restrict__ scale_W, const float* __restrict__ scale_b)
{
    int gw = blockIdx.x*8 + (threadIdx.x >> 5);
    int lane = threadIdx.x & 31;
    int b = gw >> 10, h = gw & 1023;
    const float* a = g_avg + b*EE;
    const float* w = scale_W + (size_t)h*EE;
    float s = 0.f;
    #pragma unroll
    for (int k = 0; k < 16; k++){
        int idx = k*32 + lane;
        s += a[idx] * w[idx];
    }
    #pragma unroll
    for (int o=16;o>0;o>>=1) s += __shfl_xor_sync(0xffffffffu, s, o);
    if (lane == 0){
        float v = fmaxf(s + scale_b[h], 0.f);
        g_h[b*HH + h] = v;
        g_c[b*HH + h] = v;
        g_h16[b*HH + h] = __float2half_rn(v);
    }
}

__global__ void attn_kernel(const float* __restrict__ attn_W, const int* __restrict__ src)
{
    int b = blockIdx.x, tid = threadIdx.x;
    __shared__ float sc[56];
    __shared__ float aw[56];
    int w = tid >> 5, lane = tid & 31;
    for (int s = w; s < SS; s += 8){
        const float* row = g_enc_out + (size_t)(b*SS+s)*EE;
        float a = 0.f;
        for (int e = lane; e < EE; e += 32) a += row[e]*attn_W[e];
        #pragma unroll
        for (int o=16;o>0;o>>=1) a += __shfl_xor_sync(0xffffffffu, a, o);
        if (lane==0) sc[s] = a;
    }
    __syncthreads();
    if (tid == 0){
        float mx = -1e30f;
        for (int s=0;s<SS;s++) mx = fmaxf(mx, sc[s]);
        float tot = 0.f;
        for (int s=0;s<SS;s++){
            float e = (src[b*SS+s]==0) ? 0.f : expf(sc[s]-mx);
            aw[s] = e; tot += e;
        }
        float inv = 1.f/tot;
        for (int s=0;s<SS;s++) aw[s] *= inv;
    }
    __syncthreads();
    for (int e = tid; e < EE; e += blockDim.x){
        float a = 0.f;
        #pragma unroll 5
        for (int s=0;s<SS;s++) a += aw[s]*g_enc_out[(size_t)(b*SS+s)*EE + e];
        g_ctx[b*EE + e] = a;
    }
}

__global__ __launch_bounds__(256)
void build_apre(const int* __restrict__ tgt, const float* __restrict__ dec_emb)
{
    int r = blockIdx.x;
    int b = r & 63, t = r >> 6;
    int c = threadIdx.x * 4;
    const float* srcp;
    if (c < 512){
        int tok = tgt[b*50 + t];
        srcp = dec_emb + (size_t)tok*512 + c;
    } else {
        srcp = g_ctx + b*EE + (c - 512);
    }
    float4 v = *(const float4*)srcp;
    *(ull*)(g_Apre + (size_t)r*KA + c) = pack4h(v.x, v.y, v.z, v.w);
}

__global__ __launch_bounds__(256)
void conv_wih(const float* __restrict__ W)
{
    size_t i = (size_t)blockIdx.x*blockDim.x + threadIdx.x;
    float4 v = ((const float4*)W)[i];
    *(ull*)(g_Wih16 + i*4) = pack4h(v.x, v.y, v.z, v.w);
}
__global__ __launch_bounds__(256)
void conv_whh(const float* __restrict__ W)
{
    size_t i = (size_t)blockIdx.x*blockDim.x + threadIdx.x;
    float4 v = ((const float4*)W)[i];
    *(ull*)(g_Whh16 + i*4) = pack4h(v.x, v.y, v.z, v.w);
}
__global__ __launch_bounds__(256)
void conv_w(const float* __restrict__ W)
{
    size_t i = (size_t)blockIdx.x*blockDim.x + threadIdx.x;
    float4 v = ((const float4*)W)[i];
    *(ull*)(g_Bh + i*4) = pack4h(v.x, v.y, v.z, v.w);
}

#define NSTG 4
#define TSTA 10240
#define TSTB 20480
#define SM_PROJ (NSTG*(TSTA+TSTB))
#define NKS (KA/32)

// ---- encoder GEMM: g_enc_out = A_enc . CatW^T + cat_b
__global__ __launch_bounds__(256)
void enc_mma(const float* __restrict__ bias)
{
    extern __shared__ __align__(16) char sm[];
    const uint32_t uA = smem_u32(sm);
    const uint32_t uB = uA + NSTG*TSTA;
    const int tid = threadIdx.x;
    const int wid = tid >> 5, lane = tid & 31;
    const int m0 = blockIdx.x * 128;
    const int n0 = blockIdx.y * 256;
    const int wm = wid & 3, wn = wid >> 2;

    float acc[2][16][4];
    #pragma unroll
    for (int a=0;a<2;a++)
        #pragma unroll
        for (int j=0;j<16;j++)
            #pragma unroll
            for (int x=0;x<4;x++) acc[a][j][x] = 0.f;

    const __half* gA = g_Apre + (size_t)m0*KA;
    const __half* gB = g_CatW16 + (size_t)n0*KA;

    auto load_stage = [&](int slot, int ks){
        int k0 = ks * 32;
        uint32_t sA = uA + slot*TSTA;
        uint32_t sB = uB + slot*TSTB;
        #pragma unroll
        for (int i = 0; i < 2; i++){
            int idx = tid + 256*i;
            int row = idx >> 2, lc = idx & 3;
            cpasync16(sA + row*80 + lc*16, gA + (size_t)row*KA + k0 + lc*8);
        }
        #pragma unroll
        for (int i = 0; i < 4; i++){
            int idx = tid + 256*i;
            int row = idx >> 2, lc = idx & 3;
            cpasync16(sB + row*80 + lc*16, gB + (size_t)row*KA + k0 + lc*8);
        }
        cp_commit();
    };

    load_stage(0, 0); load_stage(1, 1); load_stage(2, 2);

    const int g  = lane >> 3;
    const int lr = lane & 7;

    for (int ks = 0; ks < NKS; ks++){
        asm volatile("cp.async.wait_group 2;");
        __syncthreads();
        int ld = ks + NSTG - 1;
        if (ld < NKS) load_stage(ld & (NSTG-1), ld);
        else cp_commit();

        const uint32_t bufA = uA + (ks & (NSTG-1))*TSTA;
        const uint32_t bufB = uB + (ks & (NSTG-1))*TSTB;

        #pragma unroll
        for (int kk = 0; kk < 32; kk += 16){
            uint32_t afr[2][4];
            #pragma unroll
            for (int mi = 0; mi < 2; mi++){
                int row = wm*32 + mi*16 + ((g & 1) ? 8 : 0) + lr;
                int kof = kk + (g >> 1)*8;
                ldm4(afr[mi], bufA + row*80 + kof*2);
            }
            uint32_t bfr[8][4];
            #pragma unroll
            for (int p = 0; p < 8; p++){
                int row = wn*128 + p*16 + (g >> 1)*8 + lr;
                int kof = kk + (g & 1)*8;
                ldm4(bfr[p], bufB + row*80 + kof*2);
            }
            #pragma unroll
            for (int mi = 0; mi < 2; mi++)
                #pragma unroll
                for (int j = 0; j < 16; j++){
                    int p = j >> 1, h2 = (j & 1)*2;
                    mma16816h(acc[mi][j], afr[mi], bfr[p][h2], bfr[p][h2+1]);
                }
        }
        __syncthreads();
    }

    const int tm = lane >> 2;
    const int tn = (lane & 3)*2;
    #pragma unroll
    for (int mi = 0; mi < 2; mi++){
        #pragma unroll
        for (int j = 0; j < 16; j++){
            int gn = n0 + wn*128 + j*8 + tn;
            float2 bb = *(const float2*)(bias + gn);
            int gm0 = m0 + wm*32 + mi*16 + tm;
            {
                float2 o; o.x = acc[mi][j][0] + bb.x; o.y = acc[mi][j][1] + bb.y;
                *(float2*)(g_enc_out + (size_t)gm0*EE + gn) = o;
            }
            int gm1 = gm0 + 8;
            {
                float2 o; o.x = acc[mi][j][2] + bb.x; o.y = acc[mi][j][3] + bb.y;
                *(float2*)(g_enc_out + (size_t)gm1*EE + gn) = o;
            }
        }
    }
}

// ---- pre-GEMM: g_pre = A_pre . W_ih^T + b_ih + b_hh
__global__ __launch_bounds__(256)
void pre_mma(const float* __restrict__ b_ih, const float* __restrict__ b_hh)
{
    extern __shared__ __align__(16) char sm[];
    const uint32_t uA = smem_u32(sm);
    const uint32_t uB = uA + NSTG*TSTA;
    const int tid = threadIdx.x;
    const int wid = tid >> 5, lane = tid & 31;
    const int m0 = blockIdx.x * 128;
    const int n0 = blockIdx.y * 256;
    const int wm = wid & 3, wn = wid >> 2;

    float acc[2][16][4];
    #pragma unroll
    for (int a=0;a<2;a++)
        #pragma unroll
        for (int j=0;j<16;j++)
            #pragma unroll
            for (int x=0;x<4;x++) acc[a][j][x] = 0.f;

    const __half* gA = g_Apre + (size_t)m0*KA;
    const __half* gB = g_Wih16 + (size_t)n0*KA;

    auto load_stage = [&](int slot, int ks){
        int k0 = ks * 32;
        uint32_t sA = uA + slot*TSTA;
        uint32_t sB = uB + slot*TSTB;
        #pragma unroll
        for (int i = 0; i < 2; i++){
            int idx = tid + 256*i;
            int row = idx >> 2, lc = idx & 3;
            cpasync16(sA + row*80 + lc*16, gA + (size_t)row*KA + k0 + lc*8);
        }
        #pragma unroll
        for (int i = 0; i < 4; i++){
            int idx = tid + 256*i;
            int row = idx >> 2, lc = idx & 3;
            cpasync16(sB + row*80 + lc*16, gB + (size_t)row*KA + k0 + lc*8);
        }
        cp_commit();
    };

    load_stage(0, 0); load_stage(1, 1); load_stage(2, 2);

    const int g  = lane >> 3;
    const int lr = lane & 7;

    for (int ks = 0; ks < NKS; ks++){
        asm volatile("cp.async.wait_group 2;");
        __syncthreads();
        int ld = ks + NSTG - 1;
        if (ld < NKS) load_stage(ld & (NSTG-1), ld);
        else cp_commit();

        const uint32_t bufA = uA + (ks & (NSTG-1))*TSTA;
        const uint32_t bufB = uB + (ks & (NSTG-1))*TSTB;

        #pragma unroll
        for (int kk = 0; kk < 32; kk += 16){
            uint32_t afr[2][4];
            #pragma unroll
            for (int mi = 0; mi < 2; mi++){
                int row = wm*32 + mi*16 + ((g & 1) ? 8 : 0) + lr;
                int kof = kk + (g >> 1)*8;
                ldm4(afr[mi], bufA + row*80 + kof*2);
            }
            uint32_t bfr[8][4];
            #pragma unroll
            for (int p = 0; p < 8; p++){
                int row = wn*128 + p*16 + (g >> 1)*8 + lr;
                int kof = kk + (g & 1)*8;
                ldm4(bfr[p], bufB + row*80 + kof*2);
            }
            #pragma unroll
            for (int mi = 0; mi < 2; mi++)
                #pragma unroll
                for (int j = 0; j < 16; j++){
                    int p = j >> 1, h2 = (j & 1)*2;
                    mma16816h(acc[mi][j], afr[mi], bfr[p][h2], bfr[p][h2+1]);
                }
        }
        __syncthreads();
    }

    const int tm = lane >> 2;
    const int tn = (lane & 3)*2;
    #pragma unroll
    for (int mi = 0; mi < 2; mi++){
        #pragma unroll
        for (int j = 0; j < 16; j++){
            int gn = n0 + wn*128 + j*8 + tn;
            float2 bi = *(const float2*)(b_ih + gn);
            float2 bh = *(const float2*)(b_hh + gn);
            float bx = bi.x + bh.x, by = bi.y + bh.y;
            int gm0 = m0 + wm*32 + mi*16 + tm;
            {
                float2 o; o.x = acc[mi][j][0] + bx; o.y = acc[mi][j][1] + by;
                *(float2*)(g_pre + (size_t)gm0*G4H + gn) = o;
            }
            int gm1 = gm0 + 8;
            {
                float2 o; o.x = acc[mi][j][2] + bx; o.y = acc[mi][j][3] + by;
                *(float2*)(g_pre + (size_t)gm1*G4H + gn) = o;
            }
        }
    }
}

// ============================================================
// PERSISTENT tensor-core decoder (R14 config, best known)
// ============================================================
#define DPITCH 528
#define DSM_AS 0
#define DSM_BS (64*DPITCH)
#define DSM_TOT (DSM_BS + 128*DPITCH)

__global__ __launch_bounds__(128)
void decoder_tc(void)
{
    extern __shared__ __align__(16) char dsm[];
    const uint32_t uAs = smem_u32(dsm) + DSM_AS;
    const uint32_t uBs = smem_u32(dsm) + DSM_BS;
    const int cid = blockIdx.x;
    const int ntile = cid & 31;
    const int ksplit = cid >> 5;
    const int n0 = ntile * 128;
    const int kbase = ksplit * DKC;
    const int tid = threadIdx.x;
    const int wid = tid >> 5, lane = tid & 31;
    unsigned target = g_bepoch;

    #pragma unroll
    for (int l = 0; l < 32; l++){
        int idx = tid + 128*l;
        int n = idx >> 5, kc = (idx & 31)*8;
        uint4 v = *(const uint4*)(g_Whh16 + (size_t)(n0+n)*KA + kbase + kc);
        *(uint4*)(dsm + DSM_BS + n*DPITCH + kc*2) = v;
    }

    const int gidb = cid*128 + tid;
    float creg[4];
    #pragma unroll
    for (int e = 0; e < 4; e++) creg[e] = g_c[gidb + e*16384];

    const int g  = lane >> 3;
    const int lr = lane & 7;
    const int tm = lane >> 2;
    const int tn = (lane & 3)*2;

    for (int t = 0; t < NSTEP; t++){
        #pragma unroll
        for (int l = 0; l < 16; l++){
            int idx = tid + 128*l;
            int m = idx >> 5, kc = (idx & 31)*8;
            uint4 v = __ldcg((const uint4*)(g_h16 + m*HH + kbase + kc));
            *(uint4*)(dsm + DSM_AS + m*DPITCH + kc*2) = v;
        }
        __syncthreads();

        float acc[16][4];
        #pragma unroll
        for (int j=0;j<16;j++)
            #pragma unroll
            for (int x=0;x<4;x++) acc[j][x] = 0.f;

        #pragma unroll
        for (int kk = 0; kk < DKC; kk += 16){
            uint32_t afr[4];
            {
                int row = wid*16 + ((g & 1) ? 8 : 0) + lr;
                int kof = kk + (g >> 1)*8;
                ldm4(afr, uAs + row*DPITCH + kof*2);
            }
            uint32_t bfr[8][4];
            #pragma unroll
            for (int p = 0; p < 8; p++){
                int row = p*16 + (g >> 1)*8 + lr;
                int kof = kk + (g & 1)*8;
                ldm4(bfr[p], uBs + row*DPITCH + kof*2);
            }
            #pragma unroll
            for (int j = 0; j < 16; j++){
                int p = j >> 1, h2 = (j & 1)*2;
                mma16816h(acc[j], afr, bfr[p][h2], bfr[p][h2+1]);
            }
        }

        {
            float* outp = g_part + (size_t)ksplit*(BB*G4H);
            #pragma unroll
            for (int j = 0; j < 16; j++){
                int n = n0 + j*8 + tn;
                int m0r = wid*16 + tm;
                *(float2*)(outp + (size_t)m0r*G4H + n) =
                    make_float2(acc[j][0], acc[j][1]);
                *(float2*)(outp + (size_t)(m0r+8)*G4H + n) =
                    make_float2(acc[j][2], acc[j][3]);
            }
        }
        __syncthreads();
        gbar(target);

        #pragma unroll
        for (int e = 0; e < 4; e++){
            int gid = gidb + e*16384;
            int b = gid >> 10, h = gid & 1023;
            size_t prow = (size_t)(t*64 + b)*G4H;
            float gi = g_pre[prow + h];
            float gf = g_pre[prow + 1024 + h];
            float gg = g_pre[prow + 2048 + h];
            float go = g_pre[prow + 3072 + h];
            int base = b*G4H;
            #pragma unroll
            for (int s=0;s<DKS;s++){
                const float* p = g_part + (size_t)s*(BB*G4H) + base;
                gi += __ldcg(p + h);
                gf += __ldcg(p + 1024 + h);
                gg += __ldcg(p + 2048 + h);
                go += __ldcg(p + 3072 + h);
            }
            float c = creg[e];
            float ii = 1.f/(1.f+expf(-gi));
            float ff = 1.f/(1.f+expf(-gf));
            float oo = 1.f/(1.f+expf(-go));
            float gt = tanhf(gg);
            float cn = ff*c + ii*gt;
            float hn = oo*tanhf(cn);
            creg[e] = cn;
            __half hh = __float2half_rn(hn);
            g_h16[gid] = hh;
            g_Ah[(size_t)(t*64 + b)*KA + h] = hh;
        }
        gbar(target);
    }
}

// ============================================================
// Fallback per-step kernels (fp32 path)
// ============================================================
__global__ __launch_bounds__(128)
void gates_gemm(const float* __restrict__ W_hh)
{
    __shared__ __align__(16) float As[64*20];
    __shared__ __align__(16) float Bs[16*132];
    const int n0 = blockIdx.x * 128;
    const int kbase = blockIdx.y * KCHUNK;
    const int tid = threadIdx.x;
    const int tx = tid & 15, ty = tid >> 4;

    ull acc[8][2][2];
    #pragma unroll
    for (int i=0;i<8;i++)
        #pragma unroll
        for (int q=0;q<2;q++){ acc[i][q][0]=0ull; acc[i][q][1]=0ull; }

    for (int kt = 0; kt < KCHUNK; kt += 16){
        const int kg0 = kbase + kt;
        #pragma unroll
        for (int l=0;l<2;l++){
            int f4 = tid + 128*l;
            int row = f4 >> 2, k4 = (f4 & 3) << 2;
            float4 v = *(const float4*)(g_h + row*1024 + kg0 + k4);
            *(float4*)(As + row*20 + k4) = v;
        }
        #pragma unroll
        for (int l=0;l<4;l++){
            int f4 = tid + 128*l;
            int row = f4 >> 2, k4 = (f4 & 3) << 2;
            float4 v = *(const float4*)(W_hh + (size_t)(n0+row)*1024 + kg0 + k4);
            Bs[(k4+0)*132 + row] = v.x;
            Bs[(k4+1)*132 + row] = v.y;
            Bs[(k4+2)*132 + row] = v.z;
            Bs[(k4+3)*132 + row] = v.w;
        }
        __syncthreads();
        #pragma unroll
        for (int kq=0;kq<4;kq++){
            float4 av[8];
            #pragma unroll
            for (int i=0;i<8;i++) av[i] = *(const float4*)(As + (ty*8+i)*20 + kq*4);
            #pragma unroll
            for (int kk=0;kk<4;kk++){
                ull a2[8];
                #pragma unroll
                for (int i=0;i<8;i++){
                    float a = (kk==0)?av[i].x:(kk==1)?av[i].y:(kk==2)?av[i].z:av[i].w;
                    a2[i] = dup2(a);
                }
                const int k = kq*4+kk;
                #pragma unroll
                for (int q=0;q<2;q++){
                    ulonglong2 bv = *(const ulonglong2*)(Bs + k*132 + tx*4 + q*64);
                    #pragma unroll
                    for (int i=0;i<8;i++){ ffma2(acc[i][q][0], a2[i], bv.x);
                                           ffma2(acc[i][q][1], a2[i], bv.y); }
                }
            }
        }
        __syncthreads();
    }
    float* outp = g_part + (size_t)blockIdx.y*(BB*G4H);
    #pragma unroll
    for (int i=0;i<8;i++){
        int m = ty*8 + i;
        #pragma unroll
        for (int q=0;q<2;q++){
            int n = n0 + tx*4 + q*64;
            float2 p0 = unpk(acc[i][q][0]);
            float2 p1 = unpk(acc[i][q][1]);
            *(float4*)(outp + (size_t)m*G4H + n) = make_float4(p0.x, p0.y, p1.x, p1.y);
        }
    }
}

__global__ void lstm_pw(int t)
{
    int gid = blockIdx.x*blockDim.x + threadIdx.x;
    int b = gid >> 10, h = gid & 1023;
    size_t prow = (size_t)(t*64 + b)*G4H;
    float gi = g_pre[prow + h];
    float gf = g_pre[prow + 1024 + h];
    float gg = g_pre[prow + 2048 + h];
    float go = g_pre[prow + 3072 + h];
    int base = b*G4H;
    #pragma unroll
    for (int s=0;s<KSPLIT;s++){
        const float* p = g_part + (size_t)s*(BB*G4H) + base;
        gi += p[h]; gf += p[1024+h]; gg += p[2048+h]; go += p[3072+h];
    }
    float c  = g_c[gid];
    float ii = 1.f/(1.f+expf(-gi));
    float ff = 1.f/(1.f+expf(-gf));
    float oo = 1.f/(1.f+expf(-go));
    float gt = tanhf(gg);
    float cn = ff*c + ii*gt;
    float hn = oo*tanhf(cn);
    g_c[gid] = cn; g_h[gid] = hn;
    g_Ah[(size_t)(t*64 + b)*KA + h] = __float2half_rn(hn);
}

// ============================================================
// Projection via mma.sync fp16
// ============================================================
__global__ __launch_bounds__(256)
void proj_mma(float* __restrict__ out, const float* __restrict__ bias)
{
    extern __shared__ __align__(16) char sm[];
    const uint32_t uA = smem_u32(sm);
    const uint32_t uB = uA + NSTG*TSTA;
    const int tid = threadIdx.x;
    const int wid = tid >> 5, lane = tid & 31;
    const int m0 = blockIdx.x * 128;
    const int n0 = blockIdx.y * 256;
    const int wm = wid & 3, wn = wid >> 2;

    float acc[2][16][4];
    #pragma unroll
    for (int a=0;a<2;a++)
        #pragma unroll
        for (int j=0;j<16;j++)
            #pragma unroll
            for (int x=0;x<4;x++) acc[a][j][x] = 0.f;

    const __half* gA = g_Ah + (size_t)m0*KA;
    const __half* gB = g_Bh + (size_t)n0*KA;

    auto load_stage = [&](int slot, int ks){
        int k0 = ks * 32;
        uint32_t sA = uA + slot*TSTA;
        uint32_t sB = uB + slot*TSTB;
        #pragma unroll
        for (int i = 0; i < 2; i++){
            int idx = tid + 256*i;
            int row = idx >> 2, lc = idx & 3;
            cpasync16(sA + row*80 + lc*16, gA + (size_t)row*KA + k0 + lc*8);
        }
        #pragma unroll
        for (int i = 0; i < 4; i++){
            int idx = tid + 256*i;
            int row = idx >> 2, lc = idx & 3;
            cpasync16(sB + row*80 + lc*16, gB + (size_t)row*KA + k0 + lc*8);
        }
        cp_commit();
    };

    load_stage(0, 0); load_stage(1, 1); load_stage(2, 2);

    const int g  = lane >> 3;
    const int lr = lane & 7;

    for (int ks = 0; ks < NKS; ks++){
        asm volatile("cp.async.wait_group 2;");
        __syncthreads();
        int ld = ks + NSTG - 1;
        if (ld < NKS) load_stage(ld & (NSTG-1), ld);
        else cp_commit();

        const uint32_t bufA = uA + (ks & (NSTG-1))*TSTA;
        const uint32_t bufB = uB + (ks & (NSTG-1))*TSTB;

        #pragma unroll
        for (int kk = 0; kk < 32; kk += 16){
            uint32_t afr[2][4];
            #pragma unroll
            for (int mi = 0; mi < 2; mi++){
                int row = wm*32 + mi*16 + ((g & 1) ? 8 : 0) + lr;
                int kof = kk + (g >> 1)*8;
                ldm4(afr[mi], bufA + row*80 + kof*2);
            }
            uint32_t bfr[8][4];
            #pragma unroll
            for (int p = 0; p < 8; p++){
                int row = wn*128 + p*16 + (g >> 1)*8 + lr;
                int kof = kk + (g & 1)*8;
                ldm4(bfr[p], bufB + row*80 + kof*2);
            }
            #pragma unroll
            for (int mi = 0; mi < 2; mi++)
                #pragma unroll
                for (int j = 0; j < 16; j++){
                    int p = j >> 1, h2 = (j & 1)*2;
                    mma16816h(acc[mi][j], afr[mi], bfr[p][h2], bfr[p][h2+1]);
                }
        }
        __syncthreads();
    }

    const int tm = lane >> 2;
    const int tn = (lane & 3)*2;
    #pragma unroll
    for (int mi = 0; mi < 2; mi++){
        #pragma unroll
        for (int j = 0; j < 16; j++){
            int gn = n0 + wn*128 + j*8 + tn;
            float2 bb = *(const float2*)(bias + gn);
            int gm0 = m0 + wm*32 + mi*16 + tm;
            if (gm0 < MPROJ){
                float2 o; o.x = acc[mi][j][0] + bb.x; o.y = acc[mi][j][1] + bb.y;
                *(float2*)(out + (size_t)gm0*VTS + gn) = o;
            }
            int gm1 = gm0 + 8;
            if (gm1 < MPROJ){
                float2 o; o.x = acc[mi][j][2] + bb.x; o.y = acc[mi][j][3] + bb.y;
                *(float2*)(out + (size_t)gm1*VTS + gn) = o;
            }
        }
    }
}

extern "C" void kernel_launch(void* const* d_in, const int* in_sizes, int n_in,
                              void* d_out, int out_size)
{
    const int*   src      = (const int*)  d_in[0];
    const int*   pos      = (const int*)  d_in[2];
    const int*   tgt      = (const int*)  d_in[3];
    const float* enc_emb  = (const float*)d_in[4];
    const float* pos_emb  = (const float*)d_in[5];
    const float* cat_W    = (const float*)d_in[6];
    const float* cat_b    = (const float*)d_in[7];
    const float* scale_W  = (const float*)d_in[8];
    const float* scale_b  = (const float*)d_in[9];
    const float* dec_emb  = (const float*)d_in[10];
    const float* attn_W   = (const float*)d_in[11];
    const float* W_ih     = (const float*)d_in[13];
    const float* W_hh     = (const float*)d_in[14];
    const float* b_ih     = (const float*)d_in[15];
    const float* b_hh     = (const float*)d_in[16];
    const float* proj_W   = (const float*)d_in[17];
    const float* proj_b   = (const float*)d_in[18];
    float* out = (float*)d_out;

    // One-time setup: side stream + dependency events (R9 proved this capture
    // pattern works; here the side stream carries ONLY pure-BW conversions)
    static cudaStream_t s2 = nullptr;
    static cudaEvent_t evFork = nullptr, evCat = nullptr, evWih = nullptr,
                       evWhh = nullptr, evW = nullptr;
    static bool init_done = false;
    if (!init_done){
        cudaFuncSetAttribute(proj_mma, cudaFuncAttributeMaxDynamicSharedMemorySize, SM_PROJ);
        cudaFuncSetAttribute(pre_mma, cudaFuncAttributeMaxDynamicSharedMemorySize, SM_PROJ);
        cudaFuncSetAttribute(enc_mma, cudaFuncAttributeMaxDynamicSharedMemorySize, SM_PROJ);
        cudaFuncSetAttribute(decoder_tc, cudaFuncAttributeMaxDynamicSharedMemorySize, DSM_TOT);
        cudaStreamCreateWithFlags(&s2, cudaStreamNonBlocking);
        cudaEventCreateWithFlags(&evFork, cudaEventDisableTiming);
        cudaEventCreateWithFlags(&evCat, cudaEventDisableTiming);
        cudaEventCreateWithFlags(&evWih, cudaEventDisableTiming);
        cudaEventCreateWithFlags(&evWhh, cudaEventDisableTiming);
        cudaEventCreateWithFlags(&evW, cudaEventDisableTiming);
        init_done = true;
    }

    int per_sm = 0, n_sm = 0;
    cudaOccupancyMaxActiveBlocksPerMultiprocessor(&per_sm, decoder_tc, 128, DSM_TOT);
    cudaDeviceGetAttribute(&n_sm, cudaDevAttrMultiProcessorCount, 0);
    const bool persistent_ok = ((long)per_sm * n_sm >= DCTA);

    // Fork: all weight conversions on the side stream, ordered so the
    // earliest-needed conversion finishes first.
    cudaEventRecord(evFork, 0);
    cudaStreamWaitEvent(s2, evFork, 0);
    conv_catw<<<512, 256, 0, s2>>>(cat_W);
    cudaEventRecord(evCat, s2);
    conv_wih<<<4096, 256, 0, s2>>>(W_ih);
    cudaEventRecord(evWih, s2);
    conv_whh<<<4096, 256, 0, s2>>>(W_hh);
    cudaEventRecord(evWhh, s2);
    conv_w<<<32000, 256, 0, s2>>>(proj_W);
    cudaEventRecord(evW, s2);

    // Main chain: encoder (fp16 tensor cores)
    build_aenc<<<3200, 256>>>(src, pos, enc_emb, pos_emb);
    cudaStreamWaitEvent(0, evCat, 0);
    enc_mma<<<dim3(25,2), 256, SM_PROJ>>>(cat_b);
    avg_kernel<<<64, 512>>>();
    h0_kernel<<<8192, 256>>>(scale_W, scale_b);

    // Loop-invariant attention context + fused fp16 pre-GEMM
    attn_kernel<<<64, 256>>>(attn_W, src);
    build_apre<<<3200, 256>>>(tgt, dec_emb);
    cudaStreamWaitEvent(0, evWih, 0);
    pre_mma<<<dim3(25,16), 256, SM_PROJ>>>(b_ih, b_hh);

    // Recurrence: persistent tensor-core decoder
    cudaStreamWaitEvent(0, evWhh, 0);
    if (persistent_ok){
        decoder_tc<<<DCTA, 128, DSM_TOT>>>();
    } else {
        for (int t = 0; t < NSTEP; t++){
            gates_gemm<<<dim3(32, KSPLIT), 128>>>(W_hh);
            lstm_pw<<<256, 256>>>(t);
        }
    }

    // fp16 tensor-core projection (waits for proj_W conversion)
    cudaStreamWaitEvent(0, evW, 0);
    proj_mma<<<dim3(25,125), 256, SM_PROJ>>>(out, proj_b);
}